// round 14
// baseline (speedup 1.0000x reference)
#include <cuda_runtime.h>
#include <cuda_fp16.h>
#include <stdint.h>
#include <math.h>

#define GROUPS 4
#define DIM    512
#define NSAMP  16384
#define EPS    1e-5f
#define KSPLIT 4
#define STAGES 4

// ======================= helpers =======================
__device__ __forceinline__ uint32_t smem_to_u32(const void* p) {
    uint32_t a;
    asm("{ .reg .u64 t; cvta.to.shared.u64 t, %1; cvt.u32.u64 %0, t; }" : "=r"(a) : "l"(p));
    return a;
}
__device__ __forceinline__ void cp_async16(uint32_t dst, const void* src) {
    asm volatile("cp.async.cg.shared.global [%0], [%1], 16;" :: "r"(dst), "l"(src));
}
#define CP_COMMIT() asm volatile("cp.async.commit_group;" ::: "memory")
#define CP_WAIT2()  asm volatile("cp.async.wait_group 2;" ::: "memory")
#define CP_WAIT0()  asm volatile("cp.async.wait_group 0;" ::: "memory")
#define LDSM_X4(r0, r1, r2, r3, a) \
    asm volatile("ldmatrix.sync.aligned.m8n8.x4.shared.b16 {%0,%1,%2,%3}, [%4];" \
        : "=r"(r0), "=r"(r1), "=r"(r2), "=r"(r3) : "r"(a))
#define LDSM_X2(r0, r1, a) \
    asm volatile("ldmatrix.sync.aligned.m8n8.x2.shared.b16 {%0,%1}, [%2];" \
        : "=r"(r0), "=r"(r1) : "r"(a))
#define MMAF16(d, a, b) \
    asm volatile("mma.sync.aligned.m16n8k16.row.col.f32.f16.f16.f32 " \
        "{%0,%1,%2,%3}, {%4,%5,%6,%7}, {%8,%9}, {%0,%1,%2,%3};" \
        : "+f"((d)[0]), "+f"((d)[1]), "+f"((d)[2]), "+f"((d)[3]) \
        : "r"((a)[0]), "r"((a)[1]), "r"((a)[2]), "r"((a)[3]), "r"((b)[0]), "r"((b)[1]))

// ======================= device scratch =======================
__device__ __align__(16) float g_cs[GROUPS][256][DIM];
__device__ __align__(16) float g_mu[GROUPS][DIM];
__device__ __align__(16) float g_cv[GROUPS][DIM];
__device__ __align__(16) float g_Gpart[KSPLIT][GROUPS][DIM * DIM];
__device__ __align__(16) float g_Sf[GROUPS][DIM * DIM];
__device__ __align__(16) float g_Bf[2][GROUPS][DIM * DIM];
__device__ __align__(16) __half g_S16h[GROUPS][DIM * DIM];
__device__ __align__(16) __half g_B16h[2][GROUPS][DIM * DIM];
__device__ __align__(16) __half g_T1h[GROUPS][DIM * DIM];
__device__ __align__(16) __half g_T2h[GROUPS][DIM * DIM];
__device__ __align__(16) __half g_Z16[(size_t)GROUPS * NSAMP * DIM];   // Z row-major fp16
__device__ __align__(16) __half g_T16h[(size_t)GROUPS * DIM * NSAMP];  // Z^T fp16
__device__ float g_normpart[GROUPS][64];
__device__ float g_scale[GROUPS][2];

// ======================= fused preprocess =======================
__global__ void __launch_bounds__(256) prep_kernel(const float* __restrict__ Z) {
    __shared__ float sf[64][65];
    int g = blockIdx.z;
    int n0 = blockIdx.x * 64, d0 = blockIdx.y * 64;
    int t = threadIdx.x;

    #pragma unroll
    for (int q = 0; q < 4; q++) {
        int idx = q * 256 + t;
        int row = idx >> 4, seg = idx & 15;
        size_t goff = ((size_t)g * NSAMP + n0 + row) * DIM + d0 + seg * 4;
        float4 v = *(const float4*)(Z + goff);
        sf[row][seg * 4 + 0] = v.x;
        sf[row][seg * 4 + 1] = v.y;
        sf[row][seg * 4 + 2] = v.z;
        sf[row][seg * 4 + 3] = v.w;
        union { __half h[4]; uint2 u; } p16;
        p16.h[0] = __float2half(v.x); p16.h[1] = __float2half(v.y);
        p16.h[2] = __float2half(v.z); p16.h[3] = __float2half(v.w);
        *(uint2*)(g_Z16 + goff) = p16.u;
    }
    __syncthreads();

    if (t < 64) {
        float s = 0.f;
        #pragma unroll 8
        for (int n = 0; n < 64; n++) s += sf[n][t];
        g_cs[g][blockIdx.x][d0 + t] = s;
    }

    #pragma unroll
    for (int q = 0; q < 4; q++) {
        int idx = q * 256 + t;
        int dl = idx >> 4, nu = idx & 15;
        union { __half b[4]; uint2 u; } ph;
        #pragma unroll
        for (int k = 0; k < 4; k++)
            ph.b[k] = __float2half(sf[nu * 4 + k][dl]);
        size_t toff = ((size_t)g * DIM + d0 + dl) * NSAMP + n0 + nu * 4;
        *(uint2*)(g_T16h + toff) = ph.u;
    }
}

__global__ void mu_kernel() {
    int g = blockIdx.x, c = threadIdx.x;
    float s = 0.f;
    for (int ch = 0; ch < 256; ch++) s += g_cs[g][ch][c];
    g_mu[g][c] = s * (1.0f / NSAMP);
}

__global__ void sfin_kernel() {
    int g = blockIdx.y, b = blockIdx.x, t = threadIdx.x;
    float ss = 0.f;
    #pragma unroll
    for (int l = 0; l < 16; l++) {
        int idx = b * 4096 + l * 256 + t;
        int d = idx >> 9, e = idx & 511;
        float v = 0.f;
        #pragma unroll
        for (int s = 0; s < KSPLIT; s++) v += g_Gpart[s][g][idx];
        v -= (float)NSAMP * g_mu[g][d] * g_mu[g][e];
        if (d == e) v += EPS;
        g_Sf[g][idx] = v;
        ss += v * v;
    }
    __shared__ float red[256];
    red[t] = ss; __syncthreads();
    for (int s2 = 128; s2 > 0; s2 >>= 1) {
        if (t < s2) red[t] += red[t + s2];
        __syncthreads();
    }
    if (t == 0) g_normpart[g][b] = red[0];
}

__global__ void norm_kernel() {
    int g = blockIdx.x, t = threadIdx.x;
    __shared__ float red[64];
    red[t] = g_normpart[g][t]; __syncthreads();
    for (int s = 32; s > 0; s >>= 1) {
        if (t < s) red[t] += red[t + s];
        __syncthreads();
    }
    if (t == 0) {
        float nrm = sqrtf(red[0]);
        g_scale[g][0] = 1.0f / nrm;
        g_scale[g][1] = rsqrtf(nrm);
    }
}

// S normalized -> fp16 ; B0 = 1.5I - 0.5S -> fp32 + fp16
__global__ void nsinit_kernel() {
    int idx = blockIdx.x * 1024 + threadIdx.x;
    int g = idx >> 18;
    int r = idx & 262143;
    int d = r >> 9, e = r & 511;
    float sv = g_Sf[g][r] * g_scale[g][0];
    g_S16h[g][r] = __float2half(sv);
    float b = (d == e ? 1.5f : 0.0f) - 0.5f * sv;
    g_Bf[0][g][r] = b;
    g_B16h[0][g][r] = __float2half(b);
}

__global__ void cvec_kernel(const float* __restrict__ Bf) {
    int g = blockIdx.y;
    int warp = threadIdx.x >> 5, lane = threadIdx.x & 31;
    int j = blockIdx.x * 8 + warp;
    const float* row = Bf + (size_t)g * DIM * DIM + (size_t)j * DIM;
    float s = 0.f;
    #pragma unroll
    for (int k = 0; k < 16; k++) s += g_mu[g][lane + k * 32] * row[lane + k * 32];
    #pragma unroll
    for (int o = 16; o > 0; o >>= 1) s += __shfl_down_sync(0xFFFFFFFF, s, o);
    if (lane == 0) g_cv[g][j] = s;
}

// ======================= Gram GEMM (fp16, 1 product: Th*Th^T) =======================
__global__ void __launch_bounds__(256) mma_gram16(
    const __half* __restrict__ Th, float* __restrict__ Gp)
{
    constexpr int NF = 4;           // BN = 128
    constexpr int AT = 128 * 40;
    constexpr int BUFH = 2 * AT;

    int zz = blockIdx.z;
    int g = zz / KSPLIT, s = zz % KSPLIT;
    int it = blockIdx.y, jt = blockIdx.x;
    if (jt < it) return;
    int i0 = it * 128, j0 = jt * 128;
    const int K = NSAMP;
    const int Ks = K / KSPLIT, kBase = s * Ks;
    const int nch = Ks >> 5;
    const int K8 = K >> 3;

    const uint4* Ag = (const uint4*)(Th + (size_t)g * DIM * NSAMP + (size_t)i0 * K + kBase);
    const uint4* Bg = (const uint4*)(Th + (size_t)g * DIM * NSAMP + (size_t)j0 * K + kBase);

    extern __shared__ char smem[];
    uint32_t sb = smem_to_u32(smem);
    int tid = threadIdx.x;
    int lane = tid & 31, warp = tid >> 5;
    int wm = warp >> 2, wn = warp & 3;

    int q4 = lane >> 3, lr = lane & 7;
    uint32_t aAddr = sb + (uint32_t)(((wm * 64 + lr + (q4 & 1) * 8) * 40 + (q4 >> 1) * 8) * 2);
    int bl2 = lane & 15;
    uint32_t bAddr = sb + (uint32_t)(((wn * 32 + (bl2 & 7)) * 40 + ((bl2 >> 3) * 8)) * 2)
                   + (uint32_t)(AT * 2);

    int arow = tid >> 2, aseg = tid & 3;

    auto issueStage = [&](int c) {
        uint32_t bB = sb + (uint32_t)((c & (STAGES - 1)) * BUFH * 2);
        #pragma unroll
        for (int r = 0; r < 2; r++) {
            int row = arow + r * 64;
            cp_async16(bB + (uint32_t)((row * 40 + aseg * 8) * 2),
                       Ag + (size_t)row * K8 + c * 4 + aseg);
        }
        #pragma unroll
        for (int r = 0; r < 2; r++) {
            int row = arow + r * 64;
            cp_async16(bB + (uint32_t)((AT + row * 40 + aseg * 8) * 2),
                       Bg + (size_t)row * K8 + c * 4 + aseg);
        }
        CP_COMMIT();
    };

    float acc[4][NF][4];
    #pragma unroll
    for (int mf = 0; mf < 4; mf++)
        #pragma unroll
        for (int nf = 0; nf < NF; nf++)
            #pragma unroll
            for (int v = 0; v < 4; v++) acc[mf][nf][v] = 0.f;

    issueStage(0);
    issueStage(1);
    issueStage(2);

    for (int c = 0; c < nch; c++) {
        CP_WAIT2();
        __syncthreads();

        uint32_t bB = (uint32_t)((c & (STAGES - 1)) * BUFH * 2);
        #pragma unroll
        for (int k16 = 0; k16 < 2; k16++) {
            uint32_t bhF[NF][2];
            #pragma unroll
            for (int nf = 0; nf < NF; nf++) {
                uint32_t ad = bAddr + bB + (uint32_t)((nf * 8 * 40 + k16 * 16) * 2);
                LDSM_X2(bhF[nf][0], bhF[nf][1], ad);
            }
            #pragma unroll
            for (int mf = 0; mf < 4; mf++) {
                uint32_t ad = aAddr + bB + (uint32_t)((mf * 16 * 40 + k16 * 16) * 2);
                uint32_t ah[4];
                LDSM_X4(ah[0], ah[1], ah[2], ah[3], ad);
                #pragma unroll
                for (int nf = 0; nf < NF; nf++)
                    MMAF16(acc[mf][nf], ah, bhF[nf]);
            }
        }
        if (c + 3 < nch) issueStage(c + 3);
        else CP_COMMIT();
    }
    CP_WAIT0();

    const size_t DDl = (size_t)DIM * DIM;
    float* Cout = Gp + ((size_t)(s * GROUPS + g)) * DDl;
    int r0 = i0 + wm * 64 + (lane >> 2);
    int jc = j0 + wn * 32 + (lane & 3) * 2;
    #pragma unroll
    for (int mf = 0; mf < 4; mf++)
        #pragma unroll
        for (int nf = 0; nf < NF; nf++) {
            int r = r0 + mf * 16, j = jc + nf * 8;
            float* a = acc[mf][nf];
            *(float2*)&Cout[(size_t)r * DIM + j]       = make_float2(a[0], a[1]);
            *(float2*)&Cout[(size_t)(r + 8) * DIM + j] = make_float2(a[2], a[3]);
            if (it != jt) {
                Cout[(size_t)j * DIM + r]           = a[0];
                Cout[(size_t)(j + 1) * DIM + r]     = a[1];
                Cout[(size_t)j * DIM + r + 8]       = a[2];
                Cout[(size_t)(j + 1) * DIM + r + 8] = a[3];
            }
        }
}

// ======================= NS GEMM (fp16, 64x64 tiles, symmetric + mirror) =======================
// MODE 1: Ch = fp16(acc)  [+mirror]
// MODE 2: v = 1.5*Dm - 0.5*acc -> Cf + Ch  [+mirror]
template<int MODE>
__global__ void __launch_bounds__(256) mma_ns64(
    const __half* __restrict__ A,
    const __half* __restrict__ B,
    float* __restrict__ Cf, __half* __restrict__ Ch,
    const float* __restrict__ Dm)
{
    constexpr int AT = 64 * 40;       // halves per tile
    constexpr int BUFH = 2 * AT;      // A, B

    int g = blockIdx.z;
    int it = blockIdx.y, jt = blockIdx.x;
    if (jt < it) return;              // symmetric: upper triangle only
    int i0 = it * 64, j0 = jt * 64;
    const int K = DIM;
    const int nch = K >> 5;           // 16
    const int K8 = K >> 3;            // 64
    const size_t DDl = (size_t)DIM * DIM;

    const uint4* Ag = (const uint4*)(A + g * DDl + (size_t)i0 * K);
    const uint4* Bg = (const uint4*)(B + g * DDl + (size_t)j0 * K);

    extern __shared__ char smem[];
    uint32_t sb = smem_to_u32(smem);
    int tid = threadIdx.x;
    int lane = tid & 31, warp = tid >> 5;
    int wm = warp >> 2;               // 0..1  (32 rows each)
    int wn = warp & 3;                // 0..3  (16 cols each)

    int q4 = lane >> 3, lr = lane & 7;
    uint32_t aAddr = sb + (uint32_t)(((wm * 32 + lr + (q4 & 1) * 8) * 40 + (q4 >> 1) * 8) * 2);
    int bl2 = lane & 15;
    uint32_t bAddr = sb + (uint32_t)(((wn * 16 + (bl2 & 7)) * 40 + ((bl2 >> 3) * 8)) * 2)
                   + (uint32_t)(AT * 2);

    int arow = tid >> 2, aseg = tid & 3;   // 64 rows x 4 segs

    auto issueStage = [&](int c) {
        uint32_t bB = sb + (uint32_t)((c & (STAGES - 1)) * BUFH * 2);
        cp_async16(bB + (uint32_t)((arow * 40 + aseg * 8) * 2),
                   Ag + (size_t)arow * K8 + c * 4 + aseg);
        cp_async16(bB + (uint32_t)((AT + arow * 40 + aseg * 8) * 2),
                   Bg + (size_t)arow * K8 + c * 4 + aseg);
        CP_COMMIT();
    };

    float acc[2][2][4];
    #pragma unroll
    for (int mf = 0; mf < 2; mf++)
        #pragma unroll
        for (int nf = 0; nf < 2; nf++)
            #pragma unroll
            for (int v = 0; v < 4; v++) acc[mf][nf][v] = 0.f;

    issueStage(0);
    issueStage(1);
    issueStage(2);

    for (int c = 0; c < nch; c++) {
        CP_WAIT2();
        __syncthreads();

        uint32_t bB = (uint32_t)((c & (STAGES - 1)) * BUFH * 2);
        #pragma unroll
        for (int k16 = 0; k16 < 2; k16++) {
            uint32_t bhF[2][2];
            #pragma unroll
            for (int nf = 0; nf < 2; nf++) {
                uint32_t ad = bAddr + bB + (uint32_t)((nf * 8 * 40 + k16 * 16) * 2);
                LDSM_X2(bhF[nf][0], bhF[nf][1], ad);
            }
            #pragma unroll
            for (int mf = 0; mf < 2; mf++) {
                uint32_t ad = aAddr + bB + (uint32_t)((mf * 16 * 40 + k16 * 16) * 2);
                uint32_t ah[4];
                LDSM_X4(ah[0], ah[1], ah[2], ah[3], ad);
                #pragma unroll
                for (int nf = 0; nf < 2; nf++)
                    MMAF16(acc[mf][nf], ah, bhF[nf]);
            }
        }
        if (c + 3 < nch) issueStage(c + 3);
        else CP_COMMIT();
    }
    CP_WAIT0();

    size_t base = (size_t)g * DDl;
    int r0 = i0 + wm * 32 + (lane >> 2);
    int jc = j0 + wn * 16 + (lane & 3) * 2;
    #pragma unroll
    for (int mf = 0; mf < 2; mf++)
        #pragma unroll
        for (int nf = 0; nf < 2; nf++) {
            int r = r0 + mf * 16, j = jc + nf * 8;
            float* a = acc[mf][nf];
            #pragma unroll
            for (int e = 0; e < 4; e++) {
                int rr = r + (e >> 1) * 8, jj = j + (e & 1);
                size_t o = base + (size_t)rr * DIM + jj;
                float v = a[e];
                if (MODE == 2) v = 1.5f * Dm[o] - 0.5f * v;
                __half h = __float2half(v);
                if (MODE == 2) Cf[o] = v;
                Ch[o] = h;
                if (it != jt) {
                    size_t om = base + (size_t)jj * DIM + rr;
                    if (MODE == 2) Cf[om] = v;
                    Ch[om] = h;
                }
            }
        }
}

// ======================= final GEMM (fp16, 1 product: Z16*B16h) =======================
__global__ void __launch_bounds__(256) mma_final(
    const __half* __restrict__ A16,
    const __half* __restrict__ B16h,
    float* __restrict__ Cf)
{
    constexpr int NF = 4;
    constexpr int AT = 128 * 40;
    constexpr int BUFH = 2 * AT;

    int g = blockIdx.z;
    int it = blockIdx.y, jt = blockIdx.x;
    int i0 = it * 128, j0 = jt * 128;
    const int K = DIM;
    const int nch = K >> 5;
    const int K8 = K >> 3;

    const uint4* Ag  = (const uint4*)(A16  + (size_t)g * NSAMP * DIM + (size_t)i0 * K);
    const uint4* Bhg = (const uint4*)(B16h + (size_t)g * DIM * DIM + (size_t)j0 * K);

    extern __shared__ char smem[];
    uint32_t sb = smem_to_u32(smem);
    int tid = threadIdx.x;
    int lane = tid & 31, warp = tid >> 5;
    int wm = warp >> 2, wn = warp & 3;

    int q4 = lane >> 3, lr = lane & 7;
    uint32_t aAddr = sb + (uint32_t)(((wm * 64 + lr + (q4 & 1) * 8) * 40 + (q4 >> 1) * 8) * 2);
    int bl2 = lane & 15;
    uint32_t bAddr = sb + (uint32_t)(((wn * 32 + (bl2 & 7)) * 40 + ((bl2 >> 3) * 8)) * 2)
                   + (uint32_t)(AT * 2);

    int arow = tid >> 2, aseg = tid & 3;

    auto issueStage = [&](int c) {
        uint32_t bB = sb + (uint32_t)((c & (STAGES - 1)) * BUFH * 2);
        #pragma unroll
        for (int r = 0; r < 2; r++) {
            int row = arow + r * 64;
            cp_async16(bB + (uint32_t)((row * 40 + aseg * 8) * 2),
                       Ag + (size_t)row * K8 + c * 4 + aseg);
        }
        #pragma unroll
        for (int r = 0; r < 2; r++) {
            int row = arow + r * 64;
            cp_async16(bB + (uint32_t)((AT + row * 40 + aseg * 8) * 2),
                       Bhg + (size_t)row * K8 + c * 4 + aseg);
        }
        CP_COMMIT();
    };

    float acc[4][NF][4];
    #pragma unroll
    for (int mf = 0; mf < 4; mf++)
        #pragma unroll
        for (int nf = 0; nf < NF; nf++)
            #pragma unroll
            for (int v = 0; v < 4; v++) acc[mf][nf][v] = 0.f;

    issueStage(0);
    issueStage(1);
    issueStage(2);

    for (int c = 0; c < nch; c++) {
        CP_WAIT2();
        __syncthreads();

        uint32_t bB = (uint32_t)((c & (STAGES - 1)) * BUFH * 2);
        #pragma unroll
        for (int k16 = 0; k16 < 2; k16++) {
            uint32_t bhF[NF][2];
            #pragma unroll
            for (int nf = 0; nf < NF; nf++) {
                uint32_t ad = bAddr + bB + (uint32_t)((nf * 8 * 40 + k16 * 16) * 2);
                LDSM_X2(bhF[nf][0], bhF[nf][1], ad);
            }
            #pragma unroll
            for (int mf = 0; mf < 4; mf++) {
                uint32_t ad = aAddr + bB + (uint32_t)((mf * 16 * 40 + k16 * 16) * 2);
                uint32_t ah[4];
                LDSM_X4(ah[0], ah[1], ah[2], ah[3], ad);
                #pragma unroll
                for (int nf = 0; nf < NF; nf++)
                    MMAF16(acc[mf][nf], ah, bhF[nf]);
            }
        }
        if (c + 3 < nch) issueStage(c + 3);
        else CP_COMMIT();
    }
    CP_WAIT0();

    float scl = g_scale[g][1];
    float* Cout = Cf + (size_t)g * ((size_t)NSAMP * DIM);
    int r0 = i0 + wm * 64 + (lane >> 2);
    int jc = j0 + wn * 32 + (lane & 3) * 2;
    #pragma unroll
    for (int mf = 0; mf < 4; mf++)
        #pragma unroll
        for (int nf = 0; nf < NF; nf++) {
            int r = r0 + mf * 16, j = jc + nf * 8;
            float* a = acc[mf][nf];
            float c0 = g_cv[g][j], c1 = g_cv[g][j + 1];
            *(float2*)&Cout[(size_t)r * DIM + j] =
                make_float2(scl * (a[0] - c0), scl * (a[1] - c1));
            *(float2*)&Cout[(size_t)(r + 8) * DIM + j] =
                make_float2(scl * (a[2] - c0), scl * (a[3] - c1));
        }
}

// ======================= launch =======================
#define SMEM_GRAM (STAGES * (2 * 128 * 40) * 2)           //  81920 B
#define SMEM_NS   (STAGES * (2 * 64 * 40) * 2)            //  40960 B
#define SMEM_FIN  (STAGES * (2 * 128 * 40) * 2)           //  81920 B

extern "C" void kernel_launch(void* const* d_in, const int* in_sizes, int n_in,
                              void* d_out, int out_size) {
    (void)in_sizes; (void)n_in; (void)out_size;
    const float* in = (const float*)d_in[0];
    float* out = (float*)d_out;

    __half *Z16, *T16h, *S16h, *B16h, *T1h, *T2h;
    float *Sf, *Bf, *Gp;
    cudaGetSymbolAddress((void**)&Z16, g_Z16);
    cudaGetSymbolAddress((void**)&T16h, g_T16h);
    cudaGetSymbolAddress((void**)&S16h, g_S16h);
    cudaGetSymbolAddress((void**)&B16h, g_B16h);
    cudaGetSymbolAddress((void**)&T1h, g_T1h);
    cudaGetSymbolAddress((void**)&T2h, g_T2h);
    cudaGetSymbolAddress((void**)&Sf, g_Sf);
    cudaGetSymbolAddress((void**)&Bf, g_Bf);
    cudaGetSymbolAddress((void**)&Gp, g_Gpart);

    cudaFuncSetAttribute((const void*)mma_gram16,  cudaFuncAttributeMaxDynamicSharedMemorySize, SMEM_GRAM);
    cudaFuncSetAttribute((const void*)mma_ns64<1>, cudaFuncAttributeMaxDynamicSharedMemorySize, SMEM_NS);
    cudaFuncSetAttribute((const void*)mma_ns64<2>, cudaFuncAttributeMaxDynamicSharedMemorySize, SMEM_NS);
    cudaFuncSetAttribute((const void*)mma_final,   cudaFuncAttributeMaxDynamicSharedMemorySize, SMEM_FIN);

    const size_t DD = (size_t)DIM * DIM;
    const size_t GD = (size_t)GROUPS * DD;

    prep_kernel<<<dim3(256, 8, GROUPS), 256>>>(in);
    mu_kernel<<<GROUPS, 512>>>();

    mma_gram16<<<dim3(4, 4, GROUPS * KSPLIT), 256, SMEM_GRAM>>>(T16h, Gp);
    sfin_kernel<<<dim3(64, GROUPS), 256>>>();
    norm_kernel<<<GROUPS, 64>>>();
    nsinit_kernel<<<1024, 1024>>>();

    int cur = 0;
    for (int itr = 0; itr < 4; itr++) {
        int nxt = cur ^ 1;
        // T1 = B*B (symmetric)
        mma_ns64<1><<<dim3(8, 8, GROUPS), 256, SMEM_NS>>>(
            B16h + cur * GD, B16h + cur * GD, nullptr, T1h, nullptr);
        // T2 = T1*B (symmetric)
        mma_ns64<1><<<dim3(8, 8, GROUPS), 256, SMEM_NS>>>(
            T1h, B16h + cur * GD, nullptr, T2h, nullptr);
        // Bnext = 1.5*B - 0.5*T2*S (symmetric)
        mma_ns64<2><<<dim3(8, 8, GROUPS), 256, SMEM_NS>>>(
            T2h, S16h, Bf + nxt * GD, B16h + nxt * GD, Bf + cur * GD);
        cur = nxt;
    }

    cvec_kernel<<<dim3(64, GROUPS), 256>>>(Bf + cur * GD);

    // out = scl * (Z * B^T - 1 * (mu^T B))   [fp16 1-product]
    mma_final<<<dim3(4, 128, GROUPS), 256, SMEM_FIN>>>(Z16, B16h + cur * GD, out);
}

// round 15
// speedup vs baseline: 1.0213x; 1.0213x over previous
#include <cuda_runtime.h>
#include <cuda_fp16.h>
#include <stdint.h>
#include <math.h>

#define GROUPS 4
#define DIM    512
#define NSAMP  16384
#define EPS    1e-5f
#define KSPLIT 4
#define STAGES 4

// ======================= helpers =======================
__device__ __forceinline__ uint32_t smem_to_u32(const void* p) {
    uint32_t a;
    asm("{ .reg .u64 t; cvta.to.shared.u64 t, %1; cvt.u32.u64 %0, t; }" : "=r"(a) : "l"(p));
    return a;
}
__device__ __forceinline__ void cp_async16(uint32_t dst, const void* src) {
    asm volatile("cp.async.cg.shared.global [%0], [%1], 16;" :: "r"(dst), "l"(src));
}
#define CP_COMMIT() asm volatile("cp.async.commit_group;" ::: "memory")
#define CP_WAIT2()  asm volatile("cp.async.wait_group 2;" ::: "memory")
#define CP_WAIT0()  asm volatile("cp.async.wait_group 0;" ::: "memory")
#define LDSM_X4(r0, r1, r2, r3, a) \
    asm volatile("ldmatrix.sync.aligned.m8n8.x4.shared.b16 {%0,%1,%2,%3}, [%4];" \
        : "=r"(r0), "=r"(r1), "=r"(r2), "=r"(r3) : "r"(a))
#define LDSM_X2(r0, r1, a) \
    asm volatile("ldmatrix.sync.aligned.m8n8.x2.shared.b16 {%0,%1}, [%2];" \
        : "=r"(r0), "=r"(r1) : "r"(a))
#define MMAF16(d, a, b) \
    asm volatile("mma.sync.aligned.m16n8k16.row.col.f32.f16.f16.f32 " \
        "{%0,%1,%2,%3}, {%4,%5,%6,%7}, {%8,%9}, {%0,%1,%2,%3};" \
        : "+f"((d)[0]), "+f"((d)[1]), "+f"((d)[2]), "+f"((d)[3]) \
        : "r"((a)[0]), "r"((a)[1]), "r"((a)[2]), "r"((a)[3]), "r"((b)[0]), "r"((b)[1]))

// ======================= device scratch =======================
__device__ __align__(16) float g_cs[GROUPS][256][DIM];
__device__ __align__(16) float g_mu[GROUPS][DIM];
__device__ __align__(16) float g_cv[GROUPS][DIM];
__device__ __align__(16) float g_Gpart[KSPLIT][GROUPS][DIM * DIM];
__device__ __align__(16) float g_Sf[GROUPS][DIM * DIM];
__device__ __align__(16) float g_Bf[2][GROUPS][DIM * DIM];
__device__ __align__(16) __half g_S16h[GROUPS][DIM * DIM];
__device__ __align__(16) __half g_B16h[2][GROUPS][DIM * DIM];
__device__ __align__(16) __half g_T1h[GROUPS][DIM * DIM];
__device__ __align__(16) __half g_T2h[GROUPS][DIM * DIM];
__device__ __align__(16) __half g_Z16[(size_t)GROUPS * NSAMP * DIM];   // Z row-major fp16
__device__ __align__(16) __half g_T16h[(size_t)GROUPS * DIM * NSAMP];  // Z^T fp16
__device__ float g_normpart[GROUPS][64];
__device__ float g_scale[GROUPS][2];

// ======================= fused preprocess =======================
__global__ void __launch_bounds__(256) prep_kernel(const float* __restrict__ Z) {
    __shared__ float sf[64][65];
    int g = blockIdx.z;
    int n0 = blockIdx.x * 64, d0 = blockIdx.y * 64;
    int t = threadIdx.x;

    #pragma unroll
    for (int q = 0; q < 4; q++) {
        int idx = q * 256 + t;
        int row = idx >> 4, seg = idx & 15;
        size_t goff = ((size_t)g * NSAMP + n0 + row) * DIM + d0 + seg * 4;
        float4 v = *(const float4*)(Z + goff);
        sf[row][seg * 4 + 0] = v.x;
        sf[row][seg * 4 + 1] = v.y;
        sf[row][seg * 4 + 2] = v.z;
        sf[row][seg * 4 + 3] = v.w;
        union { __half h[4]; uint2 u; } p16;
        p16.h[0] = __float2half(v.x); p16.h[1] = __float2half(v.y);
        p16.h[2] = __float2half(v.z); p16.h[3] = __float2half(v.w);
        *(uint2*)(g_Z16 + goff) = p16.u;
    }
    __syncthreads();

    if (t < 64) {
        float s = 0.f;
        #pragma unroll 8
        for (int n = 0; n < 64; n++) s += sf[n][t];
        g_cs[g][blockIdx.x][d0 + t] = s;
    }

    #pragma unroll
    for (int q = 0; q < 4; q++) {
        int idx = q * 256 + t;
        int dl = idx >> 4, nu = idx & 15;
        union { __half b[4]; uint2 u; } ph;
        #pragma unroll
        for (int k = 0; k < 4; k++)
            ph.b[k] = __float2half(sf[nu * 4 + k][dl]);
        size_t toff = ((size_t)g * DIM + d0 + dl) * NSAMP + n0 + nu * 4;
        *(uint2*)(g_T16h + toff) = ph.u;
    }
}

__global__ void mu_kernel() {
    int g = blockIdx.x, c = threadIdx.x;
    float s = 0.f;
    for (int ch = 0; ch < 256; ch++) s += g_cs[g][ch][c];
    g_mu[g][c] = s * (1.0f / NSAMP);
}

__global__ void sfin_kernel() {
    int g = blockIdx.y, b = blockIdx.x, t = threadIdx.x;
    float ss = 0.f;
    #pragma unroll
    for (int l = 0; l < 16; l++) {
        int idx = b * 4096 + l * 256 + t;
        int d = idx >> 9, e = idx & 511;
        float v = 0.f;
        #pragma unroll
        for (int s = 0; s < KSPLIT; s++) v += g_Gpart[s][g][idx];
        v -= (float)NSAMP * g_mu[g][d] * g_mu[g][e];
        if (d == e) v += EPS;
        g_Sf[g][idx] = v;
        ss += v * v;
    }
    __shared__ float red[256];
    red[t] = ss; __syncthreads();
    for (int s2 = 128; s2 > 0; s2 >>= 1) {
        if (t < s2) red[t] += red[t + s2];
        __syncthreads();
    }
    if (t == 0) g_normpart[g][b] = red[0];
}

__global__ void norm_kernel() {
    int g = blockIdx.x, t = threadIdx.x;
    __shared__ float red[64];
    red[t] = g_normpart[g][t]; __syncthreads();
    for (int s = 32; s > 0; s >>= 1) {
        if (t < s) red[t] += red[t + s];
        __syncthreads();
    }
    if (t == 0) {
        float nrm = sqrtf(red[0]);
        g_scale[g][0] = 1.0f / nrm;
        g_scale[g][1] = rsqrtf(nrm);
    }
}

// S normalized -> fp16 ; B0 = 1.5I - 0.5S -> fp32 + fp16
__global__ void nsinit_kernel() {
    int idx = blockIdx.x * 1024 + threadIdx.x;
    int g = idx >> 18;
    int r = idx & 262143;
    int d = r >> 9, e = r & 511;
    float sv = g_Sf[g][r] * g_scale[g][0];
    g_S16h[g][r] = __float2half(sv);
    float b = (d == e ? 1.5f : 0.0f) - 0.5f * sv;
    g_Bf[0][g][r] = b;
    g_B16h[0][g][r] = __float2half(b);
}

__global__ void cvec_kernel(const float* __restrict__ Bf) {
    int g = blockIdx.y;
    int warp = threadIdx.x >> 5, lane = threadIdx.x & 31;
    int j = blockIdx.x * 8 + warp;
    const float* row = Bf + (size_t)g * DIM * DIM + (size_t)j * DIM;
    float s = 0.f;
    #pragma unroll
    for (int k = 0; k < 16; k++) s += g_mu[g][lane + k * 32] * row[lane + k * 32];
    #pragma unroll
    for (int o = 16; o > 0; o >>= 1) s += __shfl_down_sync(0xFFFFFFFF, s, o);
    if (lane == 0) g_cv[g][j] = s;
}

// ======================= Gram GEMM (fp16, 1 product: Th*Th^T) =======================
__global__ void __launch_bounds__(256) mma_gram16(
    const __half* __restrict__ Th, float* __restrict__ Gp)
{
    constexpr int NF = 4;           // BN = 128
    constexpr int AT = 128 * 40;
    constexpr int BUFH = 2 * AT;

    int zz = blockIdx.z;
    int g = zz / KSPLIT, s = zz % KSPLIT;
    int it = blockIdx.y, jt = blockIdx.x;
    if (jt < it) return;
    int i0 = it * 128, j0 = jt * 128;
    const int K = NSAMP;
    const int Ks = K / KSPLIT, kBase = s * Ks;
    const int nch = Ks >> 5;
    const int K8 = K >> 3;

    const uint4* Ag = (const uint4*)(Th + (size_t)g * DIM * NSAMP + (size_t)i0 * K + kBase);
    const uint4* Bg = (const uint4*)(Th + (size_t)g * DIM * NSAMP + (size_t)j0 * K + kBase);

    extern __shared__ char smem[];
    uint32_t sb = smem_to_u32(smem);
    int tid = threadIdx.x;
    int lane = tid & 31, warp = tid >> 5;
    int wm = warp >> 2, wn = warp & 3;

    int q4 = lane >> 3, lr = lane & 7;
    uint32_t aAddr = sb + (uint32_t)(((wm * 64 + lr + (q4 & 1) * 8) * 40 + (q4 >> 1) * 8) * 2);
    int bl2 = lane & 15;
    uint32_t bAddr = sb + (uint32_t)(((wn * 32 + (bl2 & 7)) * 40 + ((bl2 >> 3) * 8)) * 2)
                   + (uint32_t)(AT * 2);

    int arow = tid >> 2, aseg = tid & 3;

    auto issueStage = [&](int c) {
        uint32_t bB = sb + (uint32_t)((c & (STAGES - 1)) * BUFH * 2);
        #pragma unroll
        for (int r = 0; r < 2; r++) {
            int row = arow + r * 64;
            cp_async16(bB + (uint32_t)((row * 40 + aseg * 8) * 2),
                       Ag + (size_t)row * K8 + c * 4 + aseg);
        }
        #pragma unroll
        for (int r = 0; r < 2; r++) {
            int row = arow + r * 64;
            cp_async16(bB + (uint32_t)((AT + row * 40 + aseg * 8) * 2),
                       Bg + (size_t)row * K8 + c * 4 + aseg);
        }
        CP_COMMIT();
    };

    float acc[4][NF][4];
    #pragma unroll
    for (int mf = 0; mf < 4; mf++)
        #pragma unroll
        for (int nf = 0; nf < NF; nf++)
            #pragma unroll
            for (int v = 0; v < 4; v++) acc[mf][nf][v] = 0.f;

    issueStage(0);
    issueStage(1);
    issueStage(2);

    for (int c = 0; c < nch; c++) {
        CP_WAIT2();
        __syncthreads();

        uint32_t bB = (uint32_t)((c & (STAGES - 1)) * BUFH * 2);
        #pragma unroll
        for (int k16 = 0; k16 < 2; k16++) {
            uint32_t bhF[NF][2];
            #pragma unroll
            for (int nf = 0; nf < NF; nf++) {
                uint32_t ad = bAddr + bB + (uint32_t)((nf * 8 * 40 + k16 * 16) * 2);
                LDSM_X2(bhF[nf][0], bhF[nf][1], ad);
            }
            #pragma unroll
            for (int mf = 0; mf < 4; mf++) {
                uint32_t ad = aAddr + bB + (uint32_t)((mf * 16 * 40 + k16 * 16) * 2);
                uint32_t ah[4];
                LDSM_X4(ah[0], ah[1], ah[2], ah[3], ad);
                #pragma unroll
                for (int nf = 0; nf < NF; nf++)
                    MMAF16(acc[mf][nf], ah, bhF[nf]);
            }
        }
        if (c + 3 < nch) issueStage(c + 3);
        else CP_COMMIT();
    }
    CP_WAIT0();

    const size_t DDl = (size_t)DIM * DIM;
    float* Cout = Gp + ((size_t)(s * GROUPS + g)) * DDl;
    int r0 = i0 + wm * 64 + (lane >> 2);
    int jc = j0 + wn * 32 + (lane & 3) * 2;
    #pragma unroll
    for (int mf = 0; mf < 4; mf++)
        #pragma unroll
        for (int nf = 0; nf < NF; nf++) {
            int r = r0 + mf * 16, j = jc + nf * 8;
            float* a = acc[mf][nf];
            *(float2*)&Cout[(size_t)r * DIM + j]       = make_float2(a[0], a[1]);
            *(float2*)&Cout[(size_t)(r + 8) * DIM + j] = make_float2(a[2], a[3]);
            if (it != jt) {
                Cout[(size_t)j * DIM + r]           = a[0];
                Cout[(size_t)(j + 1) * DIM + r]     = a[1];
                Cout[(size_t)j * DIM + r + 8]       = a[2];
                Cout[(size_t)(j + 1) * DIM + r + 8] = a[3];
            }
        }
}

// ======================= NS GEMM (fp16, 128x64 tiles, 1 product: A*B) ============
// MODE 1: Ch = fp16(acc)
// MODE 2: v = 1.5*Dm - 0.5*acc -> Cf + Ch
template<int MODE>
__global__ void __launch_bounds__(256) mma_ns(
    const __half* __restrict__ A,
    const __half* __restrict__ B,
    float* __restrict__ Cf, __half* __restrict__ Ch,
    const float* __restrict__ Dm)
{
    constexpr int BN = 64;
    constexpr int NF = BN / 32;       // 2
    constexpr int AT = 128 * 40;
    constexpr int BT = BN * 40;
    constexpr int BUFH = AT + BT;

    int g = blockIdx.z;
    int it = blockIdx.y, jt = blockIdx.x;
    int i0 = it * 128, j0 = jt * BN;
    const int K = DIM;
    const int nch = K >> 5;
    const int K8 = K >> 3;
    const size_t DDl = (size_t)DIM * DIM;

    const uint4* Ag = (const uint4*)(A + g * DDl + (size_t)i0 * K);
    const uint4* Bg = (const uint4*)(B + g * DDl + (size_t)j0 * K);

    extern __shared__ char smem[];
    uint32_t sb = smem_to_u32(smem);
    int tid = threadIdx.x;
    int lane = tid & 31, warp = tid >> 5;
    int wm = warp >> 2, wn = warp & 3;

    int q4 = lane >> 3, lr = lane & 7;
    uint32_t aAddr = sb + (uint32_t)(((wm * 64 + lr + (q4 & 1) * 8) * 40 + (q4 >> 1) * 8) * 2);
    int bl2 = lane & 15;
    uint32_t bAddr = sb + (uint32_t)(((wn * (BN / 4) + (bl2 & 7)) * 40 + ((bl2 >> 3) * 8)) * 2)
                   + (uint32_t)(AT * 2);

    int arow = tid >> 2, aseg = tid & 3;

    auto issueStage = [&](int c) {
        uint32_t bB = sb + (uint32_t)((c & (STAGES - 1)) * BUFH * 2);
        #pragma unroll
        for (int r = 0; r < 2; r++) {
            int row = arow + r * 64;
            cp_async16(bB + (uint32_t)((row * 40 + aseg * 8) * 2),
                       Ag + (size_t)row * K8 + c * 4 + aseg);
        }
        cp_async16(bB + (uint32_t)((AT + arow * 40 + aseg * 8) * 2),
                   Bg + (size_t)arow * K8 + c * 4 + aseg);
        CP_COMMIT();
    };

    float acc[4][NF][4];
    #pragma unroll
    for (int mf = 0; mf < 4; mf++)
        #pragma unroll
        for (int nf = 0; nf < NF; nf++)
            #pragma unroll
            for (int v = 0; v < 4; v++) acc[mf][nf][v] = 0.f;

    issueStage(0);
    issueStage(1);
    issueStage(2);

    for (int c = 0; c < nch; c++) {
        CP_WAIT2();
        __syncthreads();

        uint32_t bB = (uint32_t)((c & (STAGES - 1)) * BUFH * 2);
        #pragma unroll
        for (int k16 = 0; k16 < 2; k16++) {
            uint32_t bhF[NF][2];
            #pragma unroll
            for (int nf = 0; nf < NF; nf++) {
                uint32_t ad = bAddr + bB + (uint32_t)((nf * 8 * 40 + k16 * 16) * 2);
                LDSM_X2(bhF[nf][0], bhF[nf][1], ad);
            }
            #pragma unroll
            for (int mf = 0; mf < 4; mf++) {
                uint32_t ad = aAddr + bB + (uint32_t)((mf * 16 * 40 + k16 * 16) * 2);
                uint32_t ah[4];
                LDSM_X4(ah[0], ah[1], ah[2], ah[3], ad);
                #pragma unroll
                for (int nf = 0; nf < NF; nf++)
                    MMAF16(acc[mf][nf], ah, bhF[nf]);
            }
        }
        if (c + 3 < nch) issueStage(c + 3);
        else CP_COMMIT();
    }
    CP_WAIT0();

    size_t base = (size_t)g * DDl;
    int r0 = i0 + wm * 64 + (lane >> 2);
    int jc = j0 + wn * (BN / 4) + (lane & 3) * 2;
    #pragma unroll
    for (int mf = 0; mf < 4; mf++)
        #pragma unroll
        for (int nf = 0; nf < NF; nf++) {
            int r = r0 + mf * 16, j = jc + nf * 8;
            float* a = acc[mf][nf];
            #pragma unroll
            for (int e = 0; e < 4; e++) {
                int rr = r + (e >> 1) * 8, jj = j + (e & 1);
                size_t o = base + (size_t)rr * DIM + jj;
                float v = a[e];
                if (MODE == 2) v = 1.5f * Dm[o] - 0.5f * v;
                if (MODE == 2) Cf[o] = v;
                Ch[o] = __float2half(v);
            }
        }
}

// ======================= final GEMM (fp16, 1 product: Z16*B16h) =======================
__global__ void __launch_bounds__(256) mma_final(
    const __half* __restrict__ A16,
    const __half* __restrict__ B16h,
    float* __restrict__ Cf)
{
    constexpr int NF = 4;
    constexpr int AT = 128 * 40;
    constexpr int BUFH = 2 * AT;

    int g = blockIdx.z;
    int it = blockIdx.y, jt = blockIdx.x;
    int i0 = it * 128, j0 = jt * 128;
    const int K = DIM;
    const int nch = K >> 5;
    const int K8 = K >> 3;

    const uint4* Ag  = (const uint4*)(A16  + (size_t)g * NSAMP * DIM + (size_t)i0 * K);
    const uint4* Bhg = (const uint4*)(B16h + (size_t)g * DIM * DIM + (size_t)j0 * K);

    extern __shared__ char smem[];
    uint32_t sb = smem_to_u32(smem);
    int tid = threadIdx.x;
    int lane = tid & 31, warp = tid >> 5;
    int wm = warp >> 2, wn = warp & 3;

    int q4 = lane >> 3, lr = lane & 7;
    uint32_t aAddr = sb + (uint32_t)(((wm * 64 + lr + (q4 & 1) * 8) * 40 + (q4 >> 1) * 8) * 2);
    int bl2 = lane & 15;
    uint32_t bAddr = sb + (uint32_t)(((wn * 32 + (bl2 & 7)) * 40 + ((bl2 >> 3) * 8)) * 2)
                   + (uint32_t)(AT * 2);

    int arow = tid >> 2, aseg = tid & 3;

    auto issueStage = [&](int c) {
        uint32_t bB = sb + (uint32_t)((c & (STAGES - 1)) * BUFH * 2);
        #pragma unroll
        for (int r = 0; r < 2; r++) {
            int row = arow + r * 64;
            cp_async16(bB + (uint32_t)((row * 40 + aseg * 8) * 2),
                       Ag + (size_t)row * K8 + c * 4 + aseg);
        }
        #pragma unroll
        for (int r = 0; r < 2; r++) {
            int row = arow + r * 64;
            cp_async16(bB + (uint32_t)((AT + row * 40 + aseg * 8) * 2),
                       Bhg + (size_t)row * K8 + c * 4 + aseg);
        }
        CP_COMMIT();
    };

    float acc[4][NF][4];
    #pragma unroll
    for (int mf = 0; mf < 4; mf++)
        #pragma unroll
        for (int nf = 0; nf < NF; nf++)
            #pragma unroll
            for (int v = 0; v < 4; v++) acc[mf][nf][v] = 0.f;

    issueStage(0);
    issueStage(1);
    issueStage(2);

    for (int c = 0; c < nch; c++) {
        CP_WAIT2();
        __syncthreads();

        uint32_t bB = (uint32_t)((c & (STAGES - 1)) * BUFH * 2);
        #pragma unroll
        for (int k16 = 0; k16 < 2; k16++) {
            uint32_t bhF[NF][2];
            #pragma unroll
            for (int nf = 0; nf < NF; nf++) {
                uint32_t ad = bAddr + bB + (uint32_t)((nf * 8 * 40 + k16 * 16) * 2);
                LDSM_X2(bhF[nf][0], bhF[nf][1], ad);
            }
            #pragma unroll
            for (int mf = 0; mf < 4; mf++) {
                uint32_t ad = aAddr + bB + (uint32_t)((mf * 16 * 40 + k16 * 16) * 2);
                uint32_t ah[4];
                LDSM_X4(ah[0], ah[1], ah[2], ah[3], ad);
                #pragma unroll
                for (int nf = 0; nf < NF; nf++)
                    MMAF16(acc[mf][nf], ah, bhF[nf]);
            }
        }
        if (c + 3 < nch) issueStage(c + 3);
        else CP_COMMIT();
    }
    CP_WAIT0();

    float scl = g_scale[g][1];
    float* Cout = Cf + (size_t)g * ((size_t)NSAMP * DIM);
    int r0 = i0 + wm * 64 + (lane >> 2);
    int jc = j0 + wn * 32 + (lane & 3) * 2;
    #pragma unroll
    for (int mf = 0; mf < 4; mf++)
        #pragma unroll
        for (int nf = 0; nf < NF; nf++) {
            int r = r0 + mf * 16, j = jc + nf * 8;
            float* a = acc[mf][nf];
            float c0 = g_cv[g][j], c1 = g_cv[g][j + 1];
            *(float2*)&Cout[(size_t)r * DIM + j] =
                make_float2(scl * (a[0] - c0), scl * (a[1] - c1));
            *(float2*)&Cout[(size_t)(r + 8) * DIM + j] =
                make_float2(scl * (a[2] - c0), scl * (a[3] - c1));
        }
}

// ======================= launch =======================
#define SMEM_GRAM (STAGES * (2 * 128 * 40) * 2)           //  81920 B
#define SMEM_NS   (STAGES * (128 * 40 + 64 * 40) * 2)     //  61440 B
#define SMEM_FIN  (STAGES * (2 * 128 * 40) * 2)           //  81920 B

extern "C" void kernel_launch(void* const* d_in, const int* in_sizes, int n_in,
                              void* d_out, int out_size) {
    (void)in_sizes; (void)n_in; (void)out_size;
    const float* in = (const float*)d_in[0];
    float* out = (float*)d_out;

    __half *Z16, *T16h, *S16h, *B16h, *T1h, *T2h;
    float *Sf, *Bf, *Gp;
    cudaGetSymbolAddress((void**)&Z16, g_Z16);
    cudaGetSymbolAddress((void**)&T16h, g_T16h);
    cudaGetSymbolAddress((void**)&S16h, g_S16h);
    cudaGetSymbolAddress((void**)&B16h, g_B16h);
    cudaGetSymbolAddress((void**)&T1h, g_T1h);
    cudaGetSymbolAddress((void**)&T2h, g_T2h);
    cudaGetSymbolAddress((void**)&Sf, g_Sf);
    cudaGetSymbolAddress((void**)&Bf, g_Bf);
    cudaGetSymbolAddress((void**)&Gp, g_Gpart);

    cudaFuncSetAttribute((const void*)mma_gram16, cudaFuncAttributeMaxDynamicSharedMemorySize, SMEM_GRAM);
    cudaFuncSetAttribute((const void*)mma_ns<1>,  cudaFuncAttributeMaxDynamicSharedMemorySize, SMEM_NS);
    cudaFuncSetAttribute((const void*)mma_ns<2>,  cudaFuncAttributeMaxDynamicSharedMemorySize, SMEM_NS);
    cudaFuncSetAttribute((const void*)mma_final,  cudaFuncAttributeMaxDynamicSharedMemorySize, SMEM_FIN);

    const size_t DD = (size_t)DIM * DIM;
    const size_t GD = (size_t)GROUPS * DD;

    prep_kernel<<<dim3(256, 8, GROUPS), 256>>>(in);
    mu_kernel<<<GROUPS, 512>>>();

    mma_gram16<<<dim3(4, 4, GROUPS * KSPLIT), 256, SMEM_GRAM>>>(T16h, Gp);
    sfin_kernel<<<dim3(64, GROUPS), 256>>>();
    norm_kernel<<<GROUPS, 64>>>();
    nsinit_kernel<<<1024, 1024>>>();

    int cur = 0;
    for (int itr = 0; itr < 4; itr++) {
        int nxt = cur ^ 1;
        // T1 = B*B
        mma_ns<1><<<dim3(8, 4, GROUPS), 256, SMEM_NS>>>(
            B16h + cur * GD, B16h + cur * GD, nullptr, T1h, nullptr);
        // T2 = T1*B
        mma_ns<1><<<dim3(8, 4, GROUPS), 256, SMEM_NS>>>(
            T1h, B16h + cur * GD, nullptr, T2h, nullptr);
        // Bnext = 1.5*B - 0.5*T2*S
        mma_ns<2><<<dim3(8, 4, GROUPS), 256, SMEM_NS>>>(
            T2h, S16h, Bf + nxt * GD, B16h + nxt * GD, Bf + cur * GD);
        cur = nxt;
    }

    cvec_kernel<<<dim3(64, GROUPS), 256>>>(Bf + cur * GD);

    // out = scl * (Z * B^T - 1 * (mu^T B))   [fp16 1-product]
    mma_final<<<dim3(4, 128, GROUPS), 256, SMEM_FIN>>>(Z16, B16h + cur * GD, out);
}

// round 16
// speedup vs baseline: 1.1100x; 1.0869x over previous
#include <cuda_runtime.h>
#include <cuda_fp16.h>
#include <stdint.h>
#include <math.h>

#define GROUPS 4
#define DIM    512
#define NSAMP  16384
#define EPS    1e-5f
#define KSPLIT 8
#define STAGES 4

// ======================= helpers =======================
__device__ __forceinline__ uint32_t smem_to_u32(const void* p) {
    uint32_t a;
    asm("{ .reg .u64 t; cvta.to.shared.u64 t, %1; cvt.u32.u64 %0, t; }" : "=r"(a) : "l"(p));
    return a;
}
__device__ __forceinline__ void cp_async16(uint32_t dst, const void* src) {
    asm volatile("cp.async.cg.shared.global [%0], [%1], 16;" :: "r"(dst), "l"(src));
}
#define CP_COMMIT() asm volatile("cp.async.commit_group;" ::: "memory")
#define CP_WAIT2()  asm volatile("cp.async.wait_group 2;" ::: "memory")
#define CP_WAIT0()  asm volatile("cp.async.wait_group 0;" ::: "memory")
#define LDSM_X4(r0, r1, r2, r3, a) \
    asm volatile("ldmatrix.sync.aligned.m8n8.x4.shared.b16 {%0,%1,%2,%3}, [%4];" \
        : "=r"(r0), "=r"(r1), "=r"(r2), "=r"(r3) : "r"(a))
#define LDSM_X2(r0, r1, a) \
    asm volatile("ldmatrix.sync.aligned.m8n8.x2.shared.b16 {%0,%1}, [%2];" \
        : "=r"(r0), "=r"(r1) : "r"(a))
#define MMAF16(d, a, b) \
    asm volatile("mma.sync.aligned.m16n8k16.row.col.f32.f16.f16.f32 " \
        "{%0,%1,%2,%3}, {%4,%5,%6,%7}, {%8,%9}, {%0,%1,%2,%3};" \
        : "+f"((d)[0]), "+f"((d)[1]), "+f"((d)[2]), "+f"((d)[3]) \
        : "r"((a)[0]), "r"((a)[1]), "r"((a)[2]), "r"((a)[3]), "r"((b)[0]), "r"((b)[1]))

// ======================= device scratch =======================
__device__ __align__(16) float g_cs[GROUPS][256][DIM];
__device__ __align__(16) float g_mu[GROUPS][DIM];
__device__ __align__(16) float g_cv[GROUPS][DIM];
__device__ __align__(16) float g_Gpart[KSPLIT][GROUPS][DIM * DIM];
__device__ __align__(16) float g_Sf[GROUPS][DIM * DIM];
__device__ __align__(16) float g_Bf[2][GROUPS][DIM * DIM];
__device__ __align__(16) __half g_S16h[GROUPS][DIM * DIM];
__device__ __align__(16) __half g_B16h[2][GROUPS][DIM * DIM];
__device__ __align__(16) __half g_T1h[GROUPS][DIM * DIM];   // C = B*S
__device__ __align__(16) __half g_T2h[GROUPS][DIM * DIM];   // D = B*B
__device__ __align__(16) __half g_Z16[(size_t)GROUPS * NSAMP * DIM];   // Z row-major fp16
__device__ __align__(16) __half g_T16h[(size_t)GROUPS * DIM * NSAMP];  // Z^T fp16
__device__ float g_normpart[GROUPS][64];
__device__ float g_scale[GROUPS][2];

// ======================= fused preprocess =======================
__global__ void __launch_bounds__(256) prep_kernel(const float* __restrict__ Z) {
    __shared__ float sf[64][65];
    int g = blockIdx.z;
    int n0 = blockIdx.x * 64, d0 = blockIdx.y * 64;
    int t = threadIdx.x;

    #pragma unroll
    for (int q = 0; q < 4; q++) {
        int idx = q * 256 + t;
        int row = idx >> 4, seg = idx & 15;
        size_t goff = ((size_t)g * NSAMP + n0 + row) * DIM + d0 + seg * 4;
        float4 v = *(const float4*)(Z + goff);
        sf[row][seg * 4 + 0] = v.x;
        sf[row][seg * 4 + 1] = v.y;
        sf[row][seg * 4 + 2] = v.z;
        sf[row][seg * 4 + 3] = v.w;
        union { __half h[4]; uint2 u; } p16;
        p16.h[0] = __float2half(v.x); p16.h[1] = __float2half(v.y);
        p16.h[2] = __float2half(v.z); p16.h[3] = __float2half(v.w);
        *(uint2*)(g_Z16 + goff) = p16.u;
    }
    __syncthreads();

    if (t < 64) {
        float s = 0.f;
        #pragma unroll 8
        for (int n = 0; n < 64; n++) s += sf[n][t];
        g_cs[g][blockIdx.x][d0 + t] = s;
    }

    #pragma unroll
    for (int q = 0; q < 4; q++) {
        int idx = q * 256 + t;
        int dl = idx >> 4, nu = idx & 15;
        union { __half b[4]; uint2 u; } ph;
        #pragma unroll
        for (int k = 0; k < 4; k++)
            ph.b[k] = __float2half(sf[nu * 4 + k][dl]);
        size_t toff = ((size_t)g * DIM + d0 + dl) * NSAMP + n0 + nu * 4;
        *(uint2*)(g_T16h + toff) = ph.u;
    }
}

__global__ void mu_kernel() {
    int g = blockIdx.x, c = threadIdx.x;
    float s = 0.f;
    for (int ch = 0; ch < 256; ch++) s += g_cs[g][ch][c];
    g_mu[g][c] = s * (1.0f / NSAMP);
}

__global__ void sfin_kernel() {
    int g = blockIdx.y, b = blockIdx.x, t = threadIdx.x;
    float ss = 0.f;
    #pragma unroll
    for (int l = 0; l < 16; l++) {
        int idx = b * 4096 + l * 256 + t;
        int d = idx >> 9, e = idx & 511;
        float v = 0.f;
        #pragma unroll
        for (int s = 0; s < KSPLIT; s++) v += g_Gpart[s][g][idx];
        v -= (float)NSAMP * g_mu[g][d] * g_mu[g][e];
        if (d == e) v += EPS;
        g_Sf[g][idx] = v;
        ss += v * v;
    }
    __shared__ float red[256];
    red[t] = ss; __syncthreads();
    for (int s2 = 128; s2 > 0; s2 >>= 1) {
        if (t < s2) red[t] += red[t + s2];
        __syncthreads();
    }
    if (t == 0) g_normpart[g][b] = red[0];
}

__global__ void norm_kernel() {
    int g = blockIdx.x, t = threadIdx.x;
    __shared__ float red[64];
    red[t] = g_normpart[g][t]; __syncthreads();
    for (int s = 32; s > 0; s >>= 1) {
        if (t < s) red[t] += red[t + s];
        __syncthreads();
    }
    if (t == 0) {
        float nrm = sqrtf(red[0]);
        g_scale[g][0] = 1.0f / nrm;
        g_scale[g][1] = rsqrtf(nrm);
    }
}

// S normalized -> fp16 ; B0 = 1.5I - 0.5S -> fp32 + fp16
__global__ void nsinit_kernel() {
    int idx = blockIdx.x * 1024 + threadIdx.x;
    int g = idx >> 18;
    int r = idx & 262143;
    int d = r >> 9, e = r & 511;
    float sv = g_Sf[g][r] * g_scale[g][0];
    g_S16h[g][r] = __float2half(sv);
    float b = (d == e ? 1.5f : 0.0f) - 0.5f * sv;
    g_Bf[0][g][r] = b;
    g_B16h[0][g][r] = __float2half(b);
}

__global__ void cvec_kernel(const float* __restrict__ Bf) {
    int g = blockIdx.y;
    int warp = threadIdx.x >> 5, lane = threadIdx.x & 31;
    int j = blockIdx.x * 8 + warp;
    const float* row = Bf + (size_t)g * DIM * DIM + (size_t)j * DIM;
    float s = 0.f;
    #pragma unroll
    for (int k = 0; k < 16; k++) s += g_mu[g][lane + k * 32] * row[lane + k * 32];
    #pragma unroll
    for (int o = 16; o > 0; o >>= 1) s += __shfl_down_sync(0xFFFFFFFF, s, o);
    if (lane == 0) g_cv[g][j] = s;
}

// ======================= Gram GEMM (fp16, 1 product: Th*Th^T) =======================
__global__ void __launch_bounds__(256) mma_gram16(
    const __half* __restrict__ Th, float* __restrict__ Gp)
{
    constexpr int NF = 4;           // BN = 128
    constexpr int AT = 128 * 40;
    constexpr int BUFH = 2 * AT;

    int zz = blockIdx.z;
    int g = zz / KSPLIT, s = zz % KSPLIT;
    int it = blockIdx.y, jt = blockIdx.x;
    if (jt < it) return;
    int i0 = it * 128, j0 = jt * 128;
    const int K = NSAMP;
    const int Ks = K / KSPLIT, kBase = s * Ks;
    const int nch = Ks >> 5;
    const int K8 = K >> 3;

    const uint4* Ag = (const uint4*)(Th + (size_t)g * DIM * NSAMP + (size_t)i0 * K + kBase);
    const uint4* Bg = (const uint4*)(Th + (size_t)g * DIM * NSAMP + (size_t)j0 * K + kBase);

    extern __shared__ char smem[];
    uint32_t sb = smem_to_u32(smem);
    int tid = threadIdx.x;
    int lane = tid & 31, warp = tid >> 5;
    int wm = warp >> 2, wn = warp & 3;

    int q4 = lane >> 3, lr = lane & 7;
    uint32_t aAddr = sb + (uint32_t)(((wm * 64 + lr + (q4 & 1) * 8) * 40 + (q4 >> 1) * 8) * 2);
    int bl2 = lane & 15;
    uint32_t bAddr = sb + (uint32_t)(((wn * 32 + (bl2 & 7)) * 40 + ((bl2 >> 3) * 8)) * 2)
                   + (uint32_t)(AT * 2);

    int arow = tid >> 2, aseg = tid & 3;

    auto issueStage = [&](int c) {
        uint32_t bB = sb + (uint32_t)((c & (STAGES - 1)) * BUFH * 2);
        #pragma unroll
        for (int r = 0; r < 2; r++) {
            int row = arow + r * 64;
            cp_async16(bB + (uint32_t)((row * 40 + aseg * 8) * 2),
                       Ag + (size_t)row * K8 + c * 4 + aseg);
        }
        #pragma unroll
        for (int r = 0; r < 2; r++) {
            int row = arow + r * 64;
            cp_async16(bB + (uint32_t)((AT + row * 40 + aseg * 8) * 2),
                       Bg + (size_t)row * K8 + c * 4 + aseg);
        }
        CP_COMMIT();
    };

    float acc[4][NF][4];
    #pragma unroll
    for (int mf = 0; mf < 4; mf++)
        #pragma unroll
        for (int nf = 0; nf < NF; nf++)
            #pragma unroll
            for (int v = 0; v < 4; v++) acc[mf][nf][v] = 0.f;

    issueStage(0);
    issueStage(1);
    issueStage(2);

    for (int c = 0; c < nch; c++) {
        CP_WAIT2();
        __syncthreads();

        uint32_t bB = (uint32_t)((c & (STAGES - 1)) * BUFH * 2);
        #pragma unroll
        for (int k16 = 0; k16 < 2; k16++) {
            uint32_t bhF[NF][2];
            #pragma unroll
            for (int nf = 0; nf < NF; nf++) {
                uint32_t ad = bAddr + bB + (uint32_t)((nf * 8 * 40 + k16 * 16) * 2);
                LDSM_X2(bhF[nf][0], bhF[nf][1], ad);
            }
            #pragma unroll
            for (int mf = 0; mf < 4; mf++) {
                uint32_t ad = aAddr + bB + (uint32_t)((mf * 16 * 40 + k16 * 16) * 2);
                uint32_t ah[4];
                LDSM_X4(ah[0], ah[1], ah[2], ah[3], ad);
                #pragma unroll
                for (int nf = 0; nf < NF; nf++)
                    MMAF16(acc[mf][nf], ah, bhF[nf]);
            }
        }
        if (c + 3 < nch) issueStage(c + 3);
        else CP_COMMIT();
    }
    CP_WAIT0();

    const size_t DDl = (size_t)DIM * DIM;
    float* Cout = Gp + ((size_t)(s * GROUPS + g)) * DDl;
    int r0 = i0 + wm * 64 + (lane >> 2);
    int jc = j0 + wn * 32 + (lane & 3) * 2;
    #pragma unroll
    for (int mf = 0; mf < 4; mf++)
        #pragma unroll
        for (int nf = 0; nf < NF; nf++) {
            int r = r0 + mf * 16, j = jc + nf * 8;
            float* a = acc[mf][nf];
            *(float2*)&Cout[(size_t)r * DIM + j]       = make_float2(a[0], a[1]);
            *(float2*)&Cout[(size_t)(r + 8) * DIM + j] = make_float2(a[2], a[3]);
            if (it != jt) {
                Cout[(size_t)j * DIM + r]           = a[0];
                Cout[(size_t)(j + 1) * DIM + r]     = a[1];
                Cout[(size_t)j * DIM + r + 8]       = a[2];
                Cout[(size_t)(j + 1) * DIM + r + 8] = a[3];
            }
        }
}

// ======================= NS dual GEMM: C=B*S and D=B*B in one launch ============
// grid (8, 8, GROUPS): blockIdx.y < 4 -> C = A1*B1^T ; else D = A2*B2^T
__global__ void __launch_bounds__(256) mma_ns_dual(
    const __half* __restrict__ A1, const __half* __restrict__ B1, __half* __restrict__ C1,
    const __half* __restrict__ A2, const __half* __restrict__ B2, __half* __restrict__ C2)
{
    constexpr int BN = 64;
    constexpr int NF = BN / 32;       // 2
    constexpr int AT = 128 * 40;
    constexpr int BT = BN * 40;
    constexpr int BUFH = AT + BT;

    int g = blockIdx.z;
    int jt = blockIdx.x;
    int ity = blockIdx.y;
    const __half* A; const __half* B; __half* Ch;
    int it;
    if (ity < 4) { A = A1; B = B1; Ch = C1; it = ity; }
    else         { A = A2; B = B2; Ch = C2; it = ity - 4; }
    int i0 = it * 128, j0 = jt * BN;
    const int K = DIM;
    const int nch = K >> 5;
    const int K8 = K >> 3;
    const size_t DDl = (size_t)DIM * DIM;

    const uint4* Ag = (const uint4*)(A + g * DDl + (size_t)i0 * K);
    const uint4* Bg = (const uint4*)(B + g * DDl + (size_t)j0 * K);

    extern __shared__ char smem[];
    uint32_t sb = smem_to_u32(smem);
    int tid = threadIdx.x;
    int lane = tid & 31, warp = tid >> 5;
    int wm = warp >> 2, wn = warp & 3;

    int q4 = lane >> 3, lr = lane & 7;
    uint32_t aAddr = sb + (uint32_t)(((wm * 64 + lr + (q4 & 1) * 8) * 40 + (q4 >> 1) * 8) * 2);
    int bl2 = lane & 15;
    uint32_t bAddr = sb + (uint32_t)(((wn * (BN / 4) + (bl2 & 7)) * 40 + ((bl2 >> 3) * 8)) * 2)
                   + (uint32_t)(AT * 2);

    int arow = tid >> 2, aseg = tid & 3;

    auto issueStage = [&](int c) {
        uint32_t bB = sb + (uint32_t)((c & (STAGES - 1)) * BUFH * 2);
        #pragma unroll
        for (int r = 0; r < 2; r++) {
            int row = arow + r * 64;
            cp_async16(bB + (uint32_t)((row * 40 + aseg * 8) * 2),
                       Ag + (size_t)row * K8 + c * 4 + aseg);
        }
        cp_async16(bB + (uint32_t)((AT + arow * 40 + aseg * 8) * 2),
                   Bg + (size_t)arow * K8 + c * 4 + aseg);
        CP_COMMIT();
    };

    float acc[4][NF][4];
    #pragma unroll
    for (int mf = 0; mf < 4; mf++)
        #pragma unroll
        for (int nf = 0; nf < NF; nf++)
            #pragma unroll
            for (int v = 0; v < 4; v++) acc[mf][nf][v] = 0.f;

    issueStage(0);
    issueStage(1);
    issueStage(2);

    for (int c = 0; c < nch; c++) {
        CP_WAIT2();
        __syncthreads();

        uint32_t bB = (uint32_t)((c & (STAGES - 1)) * BUFH * 2);
        #pragma unroll
        for (int k16 = 0; k16 < 2; k16++) {
            uint32_t bhF[NF][2];
            #pragma unroll
            for (int nf = 0; nf < NF; nf++) {
                uint32_t ad = bAddr + bB + (uint32_t)((nf * 8 * 40 + k16 * 16) * 2);
                LDSM_X2(bhF[nf][0], bhF[nf][1], ad);
            }
            #pragma unroll
            for (int mf = 0; mf < 4; mf++) {
                uint32_t ad = aAddr + bB + (uint32_t)((mf * 16 * 40 + k16 * 16) * 2);
                uint32_t ah[4];
                LDSM_X4(ah[0], ah[1], ah[2], ah[3], ad);
                #pragma unroll
                for (int nf = 0; nf < NF; nf++)
                    MMAF16(acc[mf][nf], ah, bhF[nf]);
            }
        }
        if (c + 3 < nch) issueStage(c + 3);
        else CP_COMMIT();
    }
    CP_WAIT0();

    size_t base = (size_t)g * DDl;
    int r0 = i0 + wm * 64 + (lane >> 2);
    int jc = j0 + wn * (BN / 4) + (lane & 3) * 2;
    #pragma unroll
    for (int mf = 0; mf < 4; mf++)
        #pragma unroll
        for (int nf = 0; nf < NF; nf++) {
            int r = r0 + mf * 16, j = jc + nf * 8;
            float* a = acc[mf][nf];
            #pragma unroll
            for (int e = 0; e < 4; e++) {
                int rr = r + (e >> 1) * 8, jj = j + (e & 1);
                Ch[base + (size_t)rr * DIM + jj] = __float2half(a[e]);
            }
        }
}

// ======================= NS combine GEMM: Bnext = 1.5*Dm - 0.5*(A*B^T) ============
__global__ void __launch_bounds__(256) mma_ns_comb(
    const __half* __restrict__ A,
    const __half* __restrict__ B,
    float* __restrict__ Cf, __half* __restrict__ Ch,
    const float* __restrict__ Dm)
{
    constexpr int BN = 64;
    constexpr int NF = BN / 32;       // 2
    constexpr int AT = 128 * 40;
    constexpr int BT = BN * 40;
    constexpr int BUFH = AT + BT;

    int g = blockIdx.z;
    int it = blockIdx.y, jt = blockIdx.x;
    int i0 = it * 128, j0 = jt * BN;
    const int K = DIM;
    const int nch = K >> 5;
    const int K8 = K >> 3;
    const size_t DDl = (size_t)DIM * DIM;

    const uint4* Ag = (const uint4*)(A + g * DDl + (size_t)i0 * K);
    const uint4* Bg = (const uint4*)(B + g * DDl + (size_t)j0 * K);

    extern __shared__ char smem[];
    uint32_t sb = smem_to_u32(smem);
    int tid = threadIdx.x;
    int lane = tid & 31, warp = tid >> 5;
    int wm = warp >> 2, wn = warp & 3;

    int q4 = lane >> 3, lr = lane & 7;
    uint32_t aAddr = sb + (uint32_t)(((wm * 64 + lr + (q4 & 1) * 8) * 40 + (q4 >> 1) * 8) * 2);
    int bl2 = lane & 15;
    uint32_t bAddr = sb + (uint32_t)(((wn * (BN / 4) + (bl2 & 7)) * 40 + ((bl2 >> 3) * 8)) * 2)
                   + (uint32_t)(AT * 2);

    int arow = tid >> 2, aseg = tid & 3;

    auto issueStage = [&](int c) {
        uint32_t bB = sb + (uint32_t)((c & (STAGES - 1)) * BUFH * 2);
        #pragma unroll
        for (int r = 0; r < 2; r++) {
            int row = arow + r * 64;
            cp_async16(bB + (uint32_t)((row * 40 + aseg * 8) * 2),
                       Ag + (size_t)row * K8 + c * 4 + aseg);
        }
        cp_async16(bB + (uint32_t)((AT + arow * 40 + aseg * 8) * 2),
                   Bg + (size_t)arow * K8 + c * 4 + aseg);
        CP_COMMIT();
    };

    float acc[4][NF][4];
    #pragma unroll
    for (int mf = 0; mf < 4; mf++)
        #pragma unroll
        for (int nf = 0; nf < NF; nf++)
            #pragma unroll
            for (int v = 0; v < 4; v++) acc[mf][nf][v] = 0.f;

    issueStage(0);
    issueStage(1);
    issueStage(2);

    for (int c = 0; c < nch; c++) {
        CP_WAIT2();
        __syncthreads();

        uint32_t bB = (uint32_t)((c & (STAGES - 1)) * BUFH * 2);
        #pragma unroll
        for (int k16 = 0; k16 < 2; k16++) {
            uint32_t bhF[NF][2];
            #pragma unroll
            for (int nf = 0; nf < NF; nf++) {
                uint32_t ad = bAddr + bB + (uint32_t)((nf * 8 * 40 + k16 * 16) * 2);
                LDSM_X2(bhF[nf][0], bhF[nf][1], ad);
            }
            #pragma unroll
            for (int mf = 0; mf < 4; mf++) {
                uint32_t ad = aAddr + bB + (uint32_t)((mf * 16 * 40 + k16 * 16) * 2);
                uint32_t ah[4];
                LDSM_X4(ah[0], ah[1], ah[2], ah[3], ad);
                #pragma unroll
                for (int nf = 0; nf < NF; nf++)
                    MMAF16(acc[mf][nf], ah, bhF[nf]);
            }
        }
        if (c + 3 < nch) issueStage(c + 3);
        else CP_COMMIT();
    }
    CP_WAIT0();

    size_t base = (size_t)g * DDl;
    int r0 = i0 + wm * 64 + (lane >> 2);
    int jc = j0 + wn * (BN / 4) + (lane & 3) * 2;
    #pragma unroll
    for (int mf = 0; mf < 4; mf++)
        #pragma unroll
        for (int nf = 0; nf < NF; nf++) {
            int r = r0 + mf * 16, j = jc + nf * 8;
            float* a = acc[mf][nf];
            #pragma unroll
            for (int e = 0; e < 4; e++) {
                int rr = r + (e >> 1) * 8, jj = j + (e & 1);
                size_t o = base + (size_t)rr * DIM + jj;
                float v = 1.5f * Dm[o] - 0.5f * a[e];
                Cf[o] = v;
                Ch[o] = __float2half(v);
            }
        }
}

// ======================= final GEMM (fp16, 1 product: Z16*B16h) =======================
__global__ void __launch_bounds__(256) mma_final(
    const __half* __restrict__ A16,
    const __half* __restrict__ B16h,
    float* __restrict__ Cf)
{
    constexpr int NF = 4;
    constexpr int AT = 128 * 40;
    constexpr int BUFH = 2 * AT;

    int g = blockIdx.z;
    int it = blockIdx.y, jt = blockIdx.x;
    int i0 = it * 128, j0 = jt * 128;
    const int K = DIM;
    const int nch = K >> 5;
    const int K8 = K >> 3;

    const uint4* Ag  = (const uint4*)(A16  + (size_t)g * NSAMP * DIM + (size_t)i0 * K);
    const uint4* Bhg = (const uint4*)(B16h + (size_t)g * DIM * DIM + (size_t)j0 * K);

    extern __shared__ char smem[];
    uint32_t sb = smem_to_u32(smem);
    int tid = threadIdx.x;
    int lane = tid & 31, warp = tid >> 5;
    int wm = warp >> 2, wn = warp & 3;

    int q4 = lane >> 3, lr = lane & 7;
    uint32_t aAddr = sb + (uint32_t)(((wm * 64 + lr + (q4 & 1) * 8) * 40 + (q4 >> 1) * 8) * 2);
    int bl2 = lane & 15;
    uint32_t bAddr = sb + (uint32_t)(((wn * 32 + (bl2 & 7)) * 40 + ((bl2 >> 3) * 8)) * 2)
                   + (uint32_t)(AT * 2);

    int arow = tid >> 2, aseg = tid & 3;

    auto issueStage = [&](int c) {
        uint32_t bB = sb + (uint32_t)((c & (STAGES - 1)) * BUFH * 2);
        #pragma unroll
        for (int r = 0; r < 2; r++) {
            int row = arow + r * 64;
            cp_async16(bB + (uint32_t)((row * 40 + aseg * 8) * 2),
                       Ag + (size_t)row * K8 + c * 4 + aseg);
        }
        #pragma unroll
        for (int r = 0; r < 2; r++) {
            int row = arow + r * 64;
            cp_async16(bB + (uint32_t)((AT + row * 40 + aseg * 8) * 2),
                       Bhg + (size_t)row * K8 + c * 4 + aseg);
        }
        CP_COMMIT();
    };

    float acc[4][NF][4];
    #pragma unroll
    for (int mf = 0; mf < 4; mf++)
        #pragma unroll
        for (int nf = 0; nf < NF; nf++)
            #pragma unroll
            for (int v = 0; v < 4; v++) acc[mf][nf][v] = 0.f;

    issueStage(0);
    issueStage(1);
    issueStage(2);

    for (int c = 0; c < nch; c++) {
        CP_WAIT2();
        __syncthreads();

        uint32_t bB = (uint32_t)((c & (STAGES - 1)) * BUFH * 2);
        #pragma unroll
        for (int k16 = 0; k16 < 2; k16++) {
            uint32_t bhF[NF][2];
            #pragma unroll
            for (int nf = 0; nf < NF; nf++) {
                uint32_t ad = bAddr + bB + (uint32_t)((nf * 8 * 40 + k16 * 16) * 2);
                LDSM_X2(bhF[nf][0], bhF[nf][1], ad);
            }
            #pragma unroll
            for (int mf = 0; mf < 4; mf++) {
                uint32_t ad = aAddr + bB + (uint32_t)((mf * 16 * 40 + k16 * 16) * 2);
                uint32_t ah[4];
                LDSM_X4(ah[0], ah[1], ah[2], ah[3], ad);
                #pragma unroll
                for (int nf = 0; nf < NF; nf++)
                    MMAF16(acc[mf][nf], ah, bhF[nf]);
            }
        }
        if (c + 3 < nch) issueStage(c + 3);
        else CP_COMMIT();
    }
    CP_WAIT0();

    float scl = g_scale[g][1];
    float* Cout = Cf + (size_t)g * ((size_t)NSAMP * DIM);
    int r0 = i0 + wm * 64 + (lane >> 2);
    int jc = j0 + wn * 32 + (lane & 3) * 2;
    #pragma unroll
    for (int mf = 0; mf < 4; mf++)
        #pragma unroll
        for (int nf = 0; nf < NF; nf++) {
            int r = r0 + mf * 16, j = jc + nf * 8;
            float* a = acc[mf][nf];
            float c0 = g_cv[g][j], c1 = g_cv[g][j + 1];
            *(float2*)&Cout[(size_t)r * DIM + j] =
                make_float2(scl * (a[0] - c0), scl * (a[1] - c1));
            *(float2*)&Cout[(size_t)(r + 8) * DIM + j] =
                make_float2(scl * (a[2] - c0), scl * (a[3] - c1));
        }
}

// ======================= launch =======================
#define SMEM_GRAM (STAGES * (2 * 128 * 40) * 2)           //  81920 B
#define SMEM_NS   (STAGES * (128 * 40 + 64 * 40) * 2)     //  61440 B
#define SMEM_FIN  (STAGES * (2 * 128 * 40) * 2)           //  81920 B

extern "C" void kernel_launch(void* const* d_in, const int* in_sizes, int n_in,
                              void* d_out, int out_size) {
    (void)in_sizes; (void)n_in; (void)out_size;
    const float* in = (const float*)d_in[0];
    float* out = (float*)d_out;

    __half *Z16, *T16h, *S16h, *B16h, *T1h, *T2h;
    float *Sf, *Bf, *Gp;
    cudaGetSymbolAddress((void**)&Z16, g_Z16);
    cudaGetSymbolAddress((void**)&T16h, g_T16h);
    cudaGetSymbolAddress((void**)&S16h, g_S16h);
    cudaGetSymbolAddress((void**)&B16h, g_B16h);
    cudaGetSymbolAddress((void**)&T1h, g_T1h);
    cudaGetSymbolAddress((void**)&T2h, g_T2h);
    cudaGetSymbolAddress((void**)&Sf, g_Sf);
    cudaGetSymbolAddress((void**)&Bf, g_Bf);
    cudaGetSymbolAddress((void**)&Gp, g_Gpart);

    cudaFuncSetAttribute((const void*)mma_gram16,   cudaFuncAttributeMaxDynamicSharedMemorySize, SMEM_GRAM);
    cudaFuncSetAttribute((const void*)mma_ns_dual,  cudaFuncAttributeMaxDynamicSharedMemorySize, SMEM_NS);
    cudaFuncSetAttribute((const void*)mma_ns_comb,  cudaFuncAttributeMaxDynamicSharedMemorySize, SMEM_NS);
    cudaFuncSetAttribute((const void*)mma_final,    cudaFuncAttributeMaxDynamicSharedMemorySize, SMEM_FIN);

    const size_t DD = (size_t)DIM * DIM;
    const size_t GD = (size_t)GROUPS * DD;

    prep_kernel<<<dim3(256, 8, GROUPS), 256>>>(in);
    mu_kernel<<<GROUPS, 512>>>();

    mma_gram16<<<dim3(4, 4, GROUPS * KSPLIT), 256, SMEM_GRAM>>>(T16h, Gp);
    sfin_kernel<<<dim3(64, GROUPS), 256>>>();
    norm_kernel<<<GROUPS, 64>>>();
    nsinit_kernel<<<1024, 1024>>>();

    int cur = 0;
    for (int itr = 0; itr < 4; itr++) {
        int nxt = cur ^ 1;
        // C = B*S  and  D = B*B   (independent; one 256-CTA launch)
        mma_ns_dual<<<dim3(8, 8, GROUPS), 256, SMEM_NS>>>(
            B16h + cur * GD, S16h, T1h,
            B16h + cur * GD, B16h + cur * GD, T2h);
        // Bnext = 1.5*B - 0.5*(D * C^T) = 1.5*B - 0.5*B^3*S
        mma_ns_comb<<<dim3(8, 4, GROUPS), 256, SMEM_NS>>>(
            T2h, T1h, Bf + nxt * GD, B16h + nxt * GD, Bf + cur * GD);
        cur = nxt;
    }

    cvec_kernel<<<dim3(64, GROUPS), 256>>>(Bf + cur * GD);

    // out = scl * (Z * B^T - 1 * (mu^T B))   [fp16 1-product]
    mma_final<<<dim3(4, 128, GROUPS), 256, SMEM_FIN>>>(Z16, B16h + cur * GD, out);
}

// round 17
// speedup vs baseline: 1.1755x; 1.0590x over previous
#include <cuda_runtime.h>
#include <cuda_fp16.h>
#include <stdint.h>
#include <math.h>

#define GROUPS 4
#define DIM    512
#define NSAMP  16384
#define EPS    1e-5f
#define KSPLIT 7
#define STAGES 4

// ======================= helpers =======================
__device__ __forceinline__ uint32_t smem_to_u32(const void* p) {
    uint32_t a;
    asm("{ .reg .u64 t; cvta.to.shared.u64 t, %1; cvt.u32.u64 %0, t; }" : "=r"(a) : "l"(p));
    return a;
}
__device__ __forceinline__ void cp_async16(uint32_t dst, const void* src) {
    asm volatile("cp.async.cg.shared.global [%0], [%1], 16;" :: "r"(dst), "l"(src));
}
#define CP_COMMIT() asm volatile("cp.async.commit_group;" ::: "memory")
#define CP_WAIT2()  asm volatile("cp.async.wait_group 2;" ::: "memory")
#define CP_WAIT0()  asm volatile("cp.async.wait_group 0;" ::: "memory")
#define LDSM_X4(r0, r1, r2, r3, a) \
    asm volatile("ldmatrix.sync.aligned.m8n8.x4.shared.b16 {%0,%1,%2,%3}, [%4];" \
        : "=r"(r0), "=r"(r1), "=r"(r2), "=r"(r3) : "r"(a))
#define LDSM_X2(r0, r1, a) \
    asm volatile("ldmatrix.sync.aligned.m8n8.x2.shared.b16 {%0,%1}, [%2];" \
        : "=r"(r0), "=r"(r1) : "r"(a))
#define MMAF16(d, a, b) \
    asm volatile("mma.sync.aligned.m16n8k16.row.col.f32.f16.f16.f32 " \
        "{%0,%1,%2,%3}, {%4,%5,%6,%7}, {%8,%9}, {%0,%1,%2,%3};" \
        : "+f"((d)[0]), "+f"((d)[1]), "+f"((d)[2]), "+f"((d)[3]) \
        : "r"((a)[0]), "r"((a)[1]), "r"((a)[2]), "r"((a)[3]), "r"((b)[0]), "r"((b)[1]))

// ======================= device scratch =======================
__device__ __align__(16) float g_cs[GROUPS][256][DIM];
__device__ __align__(16) float g_mu[GROUPS][DIM];
__device__ __align__(16) float g_cv[GROUPS][DIM];
__device__ __align__(16) float g_Gpart[KSPLIT][GROUPS][DIM * DIM];
__device__ __align__(16) float g_Sf[GROUPS][DIM * DIM];
__device__ __align__(16) float g_Bf[2][GROUPS][DIM * DIM];
__device__ __align__(16) __half g_S16h[GROUPS][DIM * DIM];
__device__ __align__(16) __half g_B16h[2][GROUPS][DIM * DIM];
__device__ __align__(16) __half g_T1h[GROUPS][DIM * DIM];   // C = B*S
__device__ __align__(16) __half g_T2h[GROUPS][DIM * DIM];   // D = B*B
__device__ __align__(16) __half g_Z16[(size_t)GROUPS * NSAMP * DIM];   // Z row-major fp16
__device__ __align__(16) __half g_T16h[(size_t)GROUPS * DIM * NSAMP];  // Z^T fp16
__device__ float g_normpart[GROUPS][64];
__device__ float g_scale[GROUPS][2];

// uneven K slabs for KSPLIT=7: slabs 0..5 = 2336 (73 chunks), slab 6 = 2368 (74 chunks)
#define SLAB_BASE   2336
#define SLAB_CHUNKS 73

// ======================= fused preprocess =======================
__global__ void __launch_bounds__(256) prep_kernel(const float* __restrict__ Z) {
    __shared__ float sf[64][65];
    int g = blockIdx.z;
    int n0 = blockIdx.x * 64, d0 = blockIdx.y * 64;
    int t = threadIdx.x;

    #pragma unroll
    for (int q = 0; q < 4; q++) {
        int idx = q * 256 + t;
        int row = idx >> 4, seg = idx & 15;
        size_t goff = ((size_t)g * NSAMP + n0 + row) * DIM + d0 + seg * 4;
        float4 v = *(const float4*)(Z + goff);
        sf[row][seg * 4 + 0] = v.x;
        sf[row][seg * 4 + 1] = v.y;
        sf[row][seg * 4 + 2] = v.z;
        sf[row][seg * 4 + 3] = v.w;
        union { __half h[4]; uint2 u; } p16;
        p16.h[0] = __float2half(v.x); p16.h[1] = __float2half(v.y);
        p16.h[2] = __float2half(v.z); p16.h[3] = __float2half(v.w);
        *(uint2*)(g_Z16 + goff) = p16.u;
    }
    __syncthreads();

    if (t < 64) {
        float s = 0.f;
        #pragma unroll 8
        for (int n = 0; n < 64; n++) s += sf[n][t];
        g_cs[g][blockIdx.x][d0 + t] = s;
    }

    #pragma unroll
    for (int q = 0; q < 4; q++) {
        int idx = q * 256 + t;
        int dl = idx >> 4, nu = idx & 15;
        union { __half b[4]; uint2 u; } ph;
        #pragma unroll
        for (int k = 0; k < 4; k++)
            ph.b[k] = __float2half(sf[nu * 4 + k][dl]);
        size_t toff = ((size_t)g * DIM + d0 + dl) * NSAMP + n0 + nu * 4;
        *(uint2*)(g_T16h + toff) = ph.u;
    }
}

__global__ void mu_kernel() {
    int g = blockIdx.x, c = threadIdx.x;
    float s = 0.f;
    for (int ch = 0; ch < 256; ch++) s += g_cs[g][ch][c];
    g_mu[g][c] = s * (1.0f / NSAMP);
}

__global__ void sfin_kernel() {
    int g = blockIdx.y, b = blockIdx.x, t = threadIdx.x;
    float ss = 0.f;
    #pragma unroll
    for (int l = 0; l < 16; l++) {
        int idx = b * 4096 + l * 256 + t;
        int d = idx >> 9, e = idx & 511;
        float v = 0.f;
        #pragma unroll
        for (int s = 0; s < KSPLIT; s++) v += g_Gpart[s][g][idx];
        v -= (float)NSAMP * g_mu[g][d] * g_mu[g][e];
        if (d == e) v += EPS;
        g_Sf[g][idx] = v;
        ss += v * v;
    }
    __shared__ float red[256];
    red[t] = ss; __syncthreads();
    for (int s2 = 128; s2 > 0; s2 >>= 1) {
        if (t < s2) red[t] += red[t + s2];
        __syncthreads();
    }
    if (t == 0) g_normpart[g][b] = red[0];
}

__global__ void norm_kernel() {
    int g = blockIdx.x, t = threadIdx.x;
    __shared__ float red[64];
    red[t] = g_normpart[g][t]; __syncthreads();
    for (int s = 32; s > 0; s >>= 1) {
        if (t < s) red[t] += red[t + s];
        __syncthreads();
    }
    if (t == 0) {
        float nrm = sqrtf(red[0]);
        g_scale[g][0] = 1.0f / nrm;
        g_scale[g][1] = rsqrtf(nrm);
    }
}

// S normalized -> fp16 ; B0 = 1.5I - 0.5S -> fp32 + fp16
__global__ void nsinit_kernel() {
    int idx = blockIdx.x * 1024 + threadIdx.x;
    int g = idx >> 18;
    int r = idx & 262143;
    int d = r >> 9, e = r & 511;
    float sv = g_Sf[g][r] * g_scale[g][0];
    g_S16h[g][r] = __float2half(sv);
    float b = (d == e ? 1.5f : 0.0f) - 0.5f * sv;
    g_Bf[0][g][r] = b;
    g_B16h[0][g][r] = __float2half(b);
}

__global__ void cvec_kernel(const float* __restrict__ Bf) {
    int g = blockIdx.y;
    int warp = threadIdx.x >> 5, lane = threadIdx.x & 31;
    int j = blockIdx.x * 8 + warp;
    const float* row = Bf + (size_t)g * DIM * DIM + (size_t)j * DIM;
    float s = 0.f;
    #pragma unroll
    for (int k = 0; k < 16; k++) s += g_mu[g][lane + k * 32] * row[lane + k * 32];
    #pragma unroll
    for (int o = 16; o > 0; o >>= 1) s += __shfl_down_sync(0xFFFFFFFF, s, o);
    if (lane == 0) g_cv[g][j] = s;
}

// ======================= Gram GEMM (fp16, 1 product: Th*Th^T, KSPLIT=7 uneven) ======
__global__ void __launch_bounds__(256) mma_gram16(
    const __half* __restrict__ Th, float* __restrict__ Gp)
{
    constexpr int NF = 4;           // BN = 128
    constexpr int AT = 128 * 40;
    constexpr int BUFH = 2 * AT;

    int zz = blockIdx.z;
    int g = zz / KSPLIT, s = zz % KSPLIT;
    int it = blockIdx.y, jt = blockIdx.x;
    if (jt < it) return;
    int i0 = it * 128, j0 = jt * 128;
    const int K = NSAMP;
    const int kBase = s * SLAB_BASE;
    const int nch = (s == KSPLIT - 1) ? (SLAB_CHUNKS + 1) : SLAB_CHUNKS;
    const int K8 = K >> 3;

    const uint4* Ag = (const uint4*)(Th + (size_t)g * DIM * NSAMP + (size_t)i0 * K + kBase);
    const uint4* Bg = (const uint4*)(Th + (size_t)g * DIM * NSAMP + (size_t)j0 * K + kBase);

    extern __shared__ char smem[];
    uint32_t sb = smem_to_u32(smem);
    int tid = threadIdx.x;
    int lane = tid & 31, warp = tid >> 5;
    int wm = warp >> 2, wn = warp & 3;

    int q4 = lane >> 3, lr = lane & 7;
    uint32_t aAddr = sb + (uint32_t)(((wm * 64 + lr + (q4 & 1) * 8) * 40 + (q4 >> 1) * 8) * 2);
    int bl2 = lane & 15;
    uint32_t bAddr = sb + (uint32_t)(((wn * 32 + (bl2 & 7)) * 40 + ((bl2 >> 3) * 8)) * 2)
                   + (uint32_t)(AT * 2);

    int arow = tid >> 2, aseg = tid & 3;

    auto issueStage = [&](int c) {
        uint32_t bB = sb + (uint32_t)((c & (STAGES - 1)) * BUFH * 2);
        #pragma unroll
        for (int r = 0; r < 2; r++) {
            int row = arow + r * 64;
            cp_async16(bB + (uint32_t)((row * 40 + aseg * 8) * 2),
                       Ag + (size_t)row * K8 + c * 4 + aseg);
        }
        #pragma unroll
        for (int r = 0; r < 2; r++) {
            int row = arow + r * 64;
            cp_async16(bB + (uint32_t)((AT + row * 40 + aseg * 8) * 2),
                       Bg + (size_t)row * K8 + c * 4 + aseg);
        }
        CP_COMMIT();
    };

    float acc[4][NF][4];
    #pragma unroll
    for (int mf = 0; mf < 4; mf++)
        #pragma unroll
        for (int nf = 0; nf < NF; nf++)
            #pragma unroll
            for (int v = 0; v < 4; v++) acc[mf][nf][v] = 0.f;

    issueStage(0);
    issueStage(1);
    issueStage(2);

    for (int c = 0; c < nch; c++) {
        CP_WAIT2();
        __syncthreads();

        uint32_t bB = (uint32_t)((c & (STAGES - 1)) * BUFH * 2);
        #pragma unroll
        for (int k16 = 0; k16 < 2; k16++) {
            uint32_t bhF[NF][2];
            #pragma unroll
            for (int nf = 0; nf < NF; nf++) {
                uint32_t ad = bAddr + bB + (uint32_t)((nf * 8 * 40 + k16 * 16) * 2);
                LDSM_X2(bhF[nf][0], bhF[nf][1], ad);
            }
            #pragma unroll
            for (int mf = 0; mf < 4; mf++) {
                uint32_t ad = aAddr + bB + (uint32_t)((mf * 16 * 40 + k16 * 16) * 2);
                uint32_t ah[4];
                LDSM_X4(ah[0], ah[1], ah[2], ah[3], ad);
                #pragma unroll
                for (int nf = 0; nf < NF; nf++)
                    MMAF16(acc[mf][nf], ah, bhF[nf]);
            }
        }
        if (c + 3 < nch) issueStage(c + 3);
        else CP_COMMIT();
    }
    CP_WAIT0();

    const size_t DDl = (size_t)DIM * DIM;
    float* Cout = Gp + ((size_t)(s * GROUPS + g)) * DDl;
    int r0 = i0 + wm * 64 + (lane >> 2);
    int jc = j0 + wn * 32 + (lane & 3) * 2;
    #pragma unroll
    for (int mf = 0; mf < 4; mf++)
        #pragma unroll
        for (int nf = 0; nf < NF; nf++) {
            int r = r0 + mf * 16, j = jc + nf * 8;
            float* a = acc[mf][nf];
            *(float2*)&Cout[(size_t)r * DIM + j]       = make_float2(a[0], a[1]);
            *(float2*)&Cout[(size_t)(r + 8) * DIM + j] = make_float2(a[2], a[3]);
            if (it != jt) {
                Cout[(size_t)j * DIM + r]           = a[0];
                Cout[(size_t)(j + 1) * DIM + r]     = a[1];
                Cout[(size_t)j * DIM + r + 8]       = a[2];
                Cout[(size_t)(j + 1) * DIM + r + 8] = a[3];
            }
        }
}

// ======================= NS dual GEMM: C=B*S and D=B*B in one launch ============
__global__ void __launch_bounds__(256) mma_ns_dual(
    const __half* __restrict__ A1, const __half* __restrict__ B1, __half* __restrict__ C1,
    const __half* __restrict__ A2, const __half* __restrict__ B2, __half* __restrict__ C2)
{
    constexpr int BN = 64;
    constexpr int NF = BN / 32;
    constexpr int AT = 128 * 40;
    constexpr int BT = BN * 40;
    constexpr int BUFH = AT + BT;

    int g = blockIdx.z;
    int jt = blockIdx.x;
    int ity = blockIdx.y;
    const __half* A; const __half* B; __half* Ch;
    int it;
    if (ity < 4) { A = A1; B = B1; Ch = C1; it = ity; }
    else         { A = A2; B = B2; Ch = C2; it = ity - 4; }
    int i0 = it * 128, j0 = jt * BN;
    const int K = DIM;
    const int nch = K >> 5;
    const int K8 = K >> 3;
    const size_t DDl = (size_t)DIM * DIM;

    const uint4* Ag = (const uint4*)(A + g * DDl + (size_t)i0 * K);
    const uint4* Bg = (const uint4*)(B + g * DDl + (size_t)j0 * K);

    extern __shared__ char smem[];
    uint32_t sb = smem_to_u32(smem);
    int tid = threadIdx.x;
    int lane = tid & 31, warp = tid >> 5;
    int wm = warp >> 2, wn = warp & 3;

    int q4 = lane >> 3, lr = lane & 7;
    uint32_t aAddr = sb + (uint32_t)(((wm * 64 + lr + (q4 & 1) * 8) * 40 + (q4 >> 1) * 8) * 2);
    int bl2 = lane & 15;
    uint32_t bAddr = sb + (uint32_t)(((wn * (BN / 4) + (bl2 & 7)) * 40 + ((bl2 >> 3) * 8)) * 2)
                   + (uint32_t)(AT * 2);

    int arow = tid >> 2, aseg = tid & 3;

    auto issueStage = [&](int c) {
        uint32_t bB = sb + (uint32_t)((c & (STAGES - 1)) * BUFH * 2);
        #pragma unroll
        for (int r = 0; r < 2; r++) {
            int row = arow + r * 64;
            cp_async16(bB + (uint32_t)((row * 40 + aseg * 8) * 2),
                       Ag + (size_t)row * K8 + c * 4 + aseg);
        }
        cp_async16(bB + (uint32_t)((AT + arow * 40 + aseg * 8) * 2),
                   Bg + (size_t)arow * K8 + c * 4 + aseg);
        CP_COMMIT();
    };

    float acc[4][NF][4];
    #pragma unroll
    for (int mf = 0; mf < 4; mf++)
        #pragma unroll
        for (int nf = 0; nf < NF; nf++)
            #pragma unroll
            for (int v = 0; v < 4; v++) acc[mf][nf][v] = 0.f;

    issueStage(0);
    issueStage(1);
    issueStage(2);

    for (int c = 0; c < nch; c++) {
        CP_WAIT2();
        __syncthreads();

        uint32_t bB = (uint32_t)((c & (STAGES - 1)) * BUFH * 2);
        #pragma unroll
        for (int k16 = 0; k16 < 2; k16++) {
            uint32_t bhF[NF][2];
            #pragma unroll
            for (int nf = 0; nf < NF; nf++) {
                uint32_t ad = bAddr + bB + (uint32_t)((nf * 8 * 40 + k16 * 16) * 2);
                LDSM_X2(bhF[nf][0], bhF[nf][1], ad);
            }
            #pragma unroll
            for (int mf = 0; mf < 4; mf++) {
                uint32_t ad = aAddr + bB + (uint32_t)((mf * 16 * 40 + k16 * 16) * 2);
                uint32_t ah[4];
                LDSM_X4(ah[0], ah[1], ah[2], ah[3], ad);
                #pragma unroll
                for (int nf = 0; nf < NF; nf++)
                    MMAF16(acc[mf][nf], ah, bhF[nf]);
            }
        }
        if (c + 3 < nch) issueStage(c + 3);
        else CP_COMMIT();
    }
    CP_WAIT0();

    size_t base = (size_t)g * DDl;
    int r0 = i0 + wm * 64 + (lane >> 2);
    int jc = j0 + wn * (BN / 4) + (lane & 3) * 2;
    #pragma unroll
    for (int mf = 0; mf < 4; mf++)
        #pragma unroll
        for (int nf = 0; nf < NF; nf++) {
            int r = r0 + mf * 16, j = jc + nf * 8;
            float* a = acc[mf][nf];
            #pragma unroll
            for (int e = 0; e < 4; e++) {
                int rr = r + (e >> 1) * 8, jj = j + (e & 1);
                Ch[base + (size_t)rr * DIM + jj] = __float2half(a[e]);
            }
        }
}

// ======================= NS combine GEMM: Bnext = 1.5*Dm - 0.5*(A*B^T) ============
__global__ void __launch_bounds__(256) mma_ns_comb(
    const __half* __restrict__ A,
    const __half* __restrict__ B,
    float* __restrict__ Cf, __half* __restrict__ Ch,
    const float* __restrict__ Dm)
{
    constexpr int BN = 64;
    constexpr int NF = BN / 32;
    constexpr int AT = 128 * 40;
    constexpr int BT = BN * 40;
    constexpr int BUFH = AT + BT;

    int g = blockIdx.z;
    int it = blockIdx.y, jt = blockIdx.x;
    int i0 = it * 128, j0 = jt * BN;
    const int K = DIM;
    const int nch = K >> 5;
    const int K8 = K >> 3;
    const size_t DDl = (size_t)DIM * DIM;

    const uint4* Ag = (const uint4*)(A + g * DDl + (size_t)i0 * K);
    const uint4* Bg = (const uint4*)(B + g * DDl + (size_t)j0 * K);

    extern __shared__ char smem[];
    uint32_t sb = smem_to_u32(smem);
    int tid = threadIdx.x;
    int lane = tid & 31, warp = tid >> 5;
    int wm = warp >> 2, wn = warp & 3;

    int q4 = lane >> 3, lr = lane & 7;
    uint32_t aAddr = sb + (uint32_t)(((wm * 64 + lr + (q4 & 1) * 8) * 40 + (q4 >> 1) * 8) * 2);
    int bl2 = lane & 15;
    uint32_t bAddr = sb + (uint32_t)(((wn * (BN / 4) + (bl2 & 7)) * 40 + ((bl2 >> 3) * 8)) * 2)
                   + (uint32_t)(AT * 2);

    int arow = tid >> 2, aseg = tid & 3;

    auto issueStage = [&](int c) {
        uint32_t bB = sb + (uint32_t)((c & (STAGES - 1)) * BUFH * 2);
        #pragma unroll
        for (int r = 0; r < 2; r++) {
            int row = arow + r * 64;
            cp_async16(bB + (uint32_t)((row * 40 + aseg * 8) * 2),
                       Ag + (size_t)row * K8 + c * 4 + aseg);
        }
        cp_async16(bB + (uint32_t)((AT + arow * 40 + aseg * 8) * 2),
                   Bg + (size_t)arow * K8 + c * 4 + aseg);
        CP_COMMIT();
    };

    float acc[4][NF][4];
    #pragma unroll
    for (int mf = 0; mf < 4; mf++)
        #pragma unroll
        for (int nf = 0; nf < NF; nf++)
            #pragma unroll
            for (int v = 0; v < 4; v++) acc[mf][nf][v] = 0.f;

    issueStage(0);
    issueStage(1);
    issueStage(2);

    for (int c = 0; c < nch; c++) {
        CP_WAIT2();
        __syncthreads();

        uint32_t bB = (uint32_t)((c & (STAGES - 1)) * BUFH * 2);
        #pragma unroll
        for (int k16 = 0; k16 < 2; k16++) {
            uint32_t bhF[NF][2];
            #pragma unroll
            for (int nf = 0; nf < NF; nf++) {
                uint32_t ad = bAddr + bB + (uint32_t)((nf * 8 * 40 + k16 * 16) * 2);
                LDSM_X2(bhF[nf][0], bhF[nf][1], ad);
            }
            #pragma unroll
            for (int mf = 0; mf < 4; mf++) {
                uint32_t ad = aAddr + bB + (uint32_t)((mf * 16 * 40 + k16 * 16) * 2);
                uint32_t ah[4];
                LDSM_X4(ah[0], ah[1], ah[2], ah[3], ad);
                #pragma unroll
                for (int nf = 0; nf < NF; nf++)
                    MMAF16(acc[mf][nf], ah, bhF[nf]);
            }
        }
        if (c + 3 < nch) issueStage(c + 3);
        else CP_COMMIT();
    }
    CP_WAIT0();

    size_t base = (size_t)g * DDl;
    int r0 = i0 + wm * 64 + (lane >> 2);
    int jc = j0 + wn * (BN / 4) + (lane & 3) * 2;
    #pragma unroll
    for (int mf = 0; mf < 4; mf++)
        #pragma unroll
        for (int nf = 0; nf < NF; nf++) {
            int r = r0 + mf * 16, j = jc + nf * 8;
            float* a = acc[mf][nf];
            #pragma unroll
            for (int e = 0; e < 4; e++) {
                int rr = r + (e >> 1) * 8, jj = j + (e & 1);
                size_t o = base + (size_t)rr * DIM + jj;
                float v = 1.5f * Dm[o] - 0.5f * a[e];
                Cf[o] = v;
                Ch[o] = __float2half(v);
            }
        }
}

// ======================= final GEMM (fp16, 1 product: Z16*B16h) =======================
__global__ void __launch_bounds__(256) mma_final(
    const __half* __restrict__ A16,
    const __half* __restrict__ B16h,
    float* __restrict__ Cf)
{
    constexpr int NF = 4;
    constexpr int AT = 128 * 40;
    constexpr int BUFH = 2 * AT;

    int g = blockIdx.z;
    int it = blockIdx.y, jt = blockIdx.x;
    int i0 = it * 128, j0 = jt * 128;
    const int K = DIM;
    const int nch = K >> 5;
    const int K8 = K >> 3;

    const uint4* Ag  = (const uint4*)(A16  + (size_t)g * NSAMP * DIM + (size_t)i0 * K);
    const uint4* Bhg = (const uint4*)(B16h + (size_t)g * DIM * DIM + (size_t)j0 * K);

    extern __shared__ char smem[];
    uint32_t sb = smem_to_u32(smem);
    int tid = threadIdx.x;
    int lane = tid & 31, warp = tid >> 5;
    int wm = warp >> 2, wn = warp & 3;

    int q4 = lane >> 3, lr = lane & 7;
    uint32_t aAddr = sb + (uint32_t)(((wm * 64 + lr + (q4 & 1) * 8) * 40 + (q4 >> 1) * 8) * 2);
    int bl2 = lane & 15;
    uint32_t bAddr = sb + (uint32_t)(((wn * 32 + (bl2 & 7)) * 40 + ((bl2 >> 3) * 8)) * 2)
                   + (uint32_t)(AT * 2);

    int arow = tid >> 2, aseg = tid & 3;

    auto issueStage = [&](int c) {
        uint32_t bB = sb + (uint32_t)((c & (STAGES - 1)) * BUFH * 2);
        #pragma unroll
        for (int r = 0; r < 2; r++) {
            int row = arow + r * 64;
            cp_async16(bB + (uint32_t)((row * 40 + aseg * 8) * 2),
                       Ag + (size_t)row * K8 + c * 4 + aseg);
        }
        #pragma unroll
        for (int r = 0; r < 2; r++) {
            int row = arow + r * 64;
            cp_async16(bB + (uint32_t)((AT + row * 40 + aseg * 8) * 2),
                       Bhg + (size_t)row * K8 + c * 4 + aseg);
        }
        CP_COMMIT();
    };

    float acc[4][NF][4];
    #pragma unroll
    for (int mf = 0; mf < 4; mf++)
        #pragma unroll
        for (int nf = 0; nf < NF; nf++)
            #pragma unroll
            for (int v = 0; v < 4; v++) acc[mf][nf][v] = 0.f;

    issueStage(0);
    issueStage(1);
    issueStage(2);

    for (int c = 0; c < nch; c++) {
        CP_WAIT2();
        __syncthreads();

        uint32_t bB = (uint32_t)((c & (STAGES - 1)) * BUFH * 2);
        #pragma unroll
        for (int k16 = 0; k16 < 2; k16++) {
            uint32_t bhF[NF][2];
            #pragma unroll
            for (int nf = 0; nf < NF; nf++) {
                uint32_t ad = bAddr + bB + (uint32_t)((nf * 8 * 40 + k16 * 16) * 2);
                LDSM_X2(bhF[nf][0], bhF[nf][1], ad);
            }
            #pragma unroll
            for (int mf = 0; mf < 4; mf++) {
                uint32_t ad = aAddr + bB + (uint32_t)((mf * 16 * 40 + k16 * 16) * 2);
                uint32_t ah[4];
                LDSM_X4(ah[0], ah[1], ah[2], ah[3], ad);
                #pragma unroll
                for (int nf = 0; nf < NF; nf++)
                    MMAF16(acc[mf][nf], ah, bhF[nf]);
            }
        }
        if (c + 3 < nch) issueStage(c + 3);
        else CP_COMMIT();
    }
    CP_WAIT0();

    float scl = g_scale[g][1];
    float* Cout = Cf + (size_t)g * ((size_t)NSAMP * DIM);
    int r0 = i0 + wm * 64 + (lane >> 2);
    int jc = j0 + wn * 32 + (lane & 3) * 2;
    #pragma unroll
    for (int mf = 0; mf < 4; mf++)
        #pragma unroll
        for (int nf = 0; nf < NF; nf++) {
            int r = r0 + mf * 16, j = jc + nf * 8;
            float* a = acc[mf][nf];
            float c0 = g_cv[g][j], c1 = g_cv[g][j + 1];
            *(float2*)&Cout[(size_t)r * DIM + j] =
                make_float2(scl * (a[0] - c0), scl * (a[1] - c1));
            *(float2*)&Cout[(size_t)(r + 8) * DIM + j] =
                make_float2(scl * (a[2] - c0), scl * (a[3] - c1));
        }
}

// ======================= launch =======================
#define SMEM_GRAM (STAGES * (2 * 128 * 40) * 2)           //  81920 B
#define SMEM_NS   (STAGES * (128 * 40 + 64 * 40) * 2)     //  61440 B
#define SMEM_FIN  (STAGES * (2 * 128 * 40) * 2)           //  81920 B

extern "C" void kernel_launch(void* const* d_in, const int* in_sizes, int n_in,
                              void* d_out, int out_size) {
    (void)in_sizes; (void)n_in; (void)out_size;
    const float* in = (const float*)d_in[0];
    float* out = (float*)d_out;

    __half *Z16, *T16h, *S16h, *B16h, *T1h, *T2h;
    float *Sf, *Bf, *Gp;
    cudaGetSymbolAddress((void**)&Z16, g_Z16);
    cudaGetSymbolAddress((void**)&T16h, g_T16h);
    cudaGetSymbolAddress((void**)&S16h, g_S16h);
    cudaGetSymbolAddress((void**)&B16h, g_B16h);
    cudaGetSymbolAddress((void**)&T1h, g_T1h);
    cudaGetSymbolAddress((void**)&T2h, g_T2h);
    cudaGetSymbolAddress((void**)&Sf, g_Sf);
    cudaGetSymbolAddress((void**)&Bf, g_Bf);
    cudaGetSymbolAddress((void**)&Gp, g_Gpart);

    cudaFuncSetAttribute((const void*)mma_gram16,   cudaFuncAttributeMaxDynamicSharedMemorySize, SMEM_GRAM);
    cudaFuncSetAttribute((const void*)mma_ns_dual,  cudaFuncAttributeMaxDynamicSharedMemorySize, SMEM_NS);
    cudaFuncSetAttribute((const void*)mma_ns_comb,  cudaFuncAttributeMaxDynamicSharedMemorySize, SMEM_NS);
    cudaFuncSetAttribute((const void*)mma_final,    cudaFuncAttributeMaxDynamicSharedMemorySize, SMEM_FIN);

    const size_t DD = (size_t)DIM * DIM;
    const size_t GD = (size_t)GROUPS * DD;

    prep_kernel<<<dim3(256, 8, GROUPS), 256>>>(in);
    mu_kernel<<<GROUPS, 512>>>();

    mma_gram16<<<dim3(4, 4, GROUPS * KSPLIT), 256, SMEM_GRAM>>>(T16h, Gp);
    sfin_kernel<<<dim3(64, GROUPS), 256>>>();
    norm_kernel<<<GROUPS, 64>>>();
    nsinit_kernel<<<1024, 1024>>>();

    int cur = 0;
    for (int itr = 0; itr < 4; itr++) {
        int nxt = cur ^ 1;
        // C = B*S  and  D = B*B   (independent; one 256-CTA launch)
        mma_ns_dual<<<dim3(8, 8, GROUPS), 256, SMEM_NS>>>(
            B16h + cur * GD, S16h, T1h,
            B16h + cur * GD, B16h + cur * GD, T2h);
        // Bnext = 1.5*B - 0.5*(D * C^T) = 1.5*B - 0.5*B^3*S
        mma_ns_comb<<<dim3(8, 4, GROUPS), 256, SMEM_NS>>>(
            T2h, T1h, Bf + nxt * GD, B16h + nxt * GD, Bf + cur * GD);
        cur = nxt;
    }

    cvec_kernel<<<dim3(64, GROUPS), 256>>>(Bf + cur * GD);

    // out = scl * (Z * B^T - 1 * (mu^T B))   [fp16 1-product]
    mma_final<<<dim3(4, 128, GROUPS), 256, SMEM_FIN>>>(Z16, B16h + cur * GD, out);
}